// round 1
// baseline (speedup 1.0000x reference)
#include <cuda_runtime.h>
#include <math.h>

#define H_  16
#define D_  64
#define DM  1024
#define BATCH 2
#define NQ  2048
#define NC  2048
#define MQ  (BATCH*NQ)   // 4096
#define MC  (BATCH*NC)   // 4096

// ---------------- scratch ----------------
__device__ float g_rawq[MQ * DM];            // 16 MB
__device__ float g_rawkv[MC * 2 * DM];       // 32 MB
__device__ float g_q[BATCH*H_*NQ*D_];        // 16 MB  [b,h,n,d]  (LN'd, *8)
__device__ float g_k[BATCH*H_*NC*D_];        // 16 MB  [b,h,n,d]  (LN'd)
__device__ float g_v[BATCH*H_*NC*D_];        // 16 MB  [b,h,n,d]
__device__ float g_o[MQ * DM];               // 16 MB  [b,n,(h d)]

// ---------------- GEMM: C[M,N] = A[M,K] @ B[K,N] (+bias) ----------------
// row-major, M,N %64 == 0, K %16 == 0. 256 threads, 64x64 tile, 4x4/thread.
__global__ __launch_bounds__(256) void gemm_kernel(
    const float* __restrict__ A, const float* __restrict__ B,
    float* __restrict__ C, const float* __restrict__ bias,
    int M, int N, int K)
{
    __shared__ float As[16][64];   // [k][m]
    __shared__ float Bs[16][64];   // [k][n]
    const int t  = threadIdx.x;
    const int tx = t & 15, ty = t >> 4;
    const int m0 = blockIdx.y * 64, n0 = blockIdx.x * 64;
    const int lrow = t >> 2,  lk   = (t & 3) << 2;   // A: row 0..63, k 0/4/8/12
    const int brow = t >> 4,  bcol = (t & 15) << 2;  // B: k 0..15,  n 0..60

    const float* Ag = A + (size_t)(m0 + lrow) * K + lk;
    const float* Bg = B + (size_t)brow * N + n0 + bcol;

    float acc[4][4] = {};
    for (int k0 = 0; k0 < K; k0 += 16) {
        float4 av = *(const float4*)(Ag + k0);
        float4 bv = *(const float4*)(Bg + (size_t)k0 * N);
        __syncthreads();
        As[lk+0][lrow] = av.x; As[lk+1][lrow] = av.y;
        As[lk+2][lrow] = av.z; As[lk+3][lrow] = av.w;
        *(float4*)&Bs[brow][bcol] = bv;
        __syncthreads();
#pragma unroll
        for (int kk = 0; kk < 16; kk++) {
            float a[4], b[4];
            *(float4*)a = *(const float4*)&As[kk][ty << 2];
            *(float4*)b = *(const float4*)&Bs[kk][tx << 2];
#pragma unroll
            for (int i = 0; i < 4; i++)
#pragma unroll
                for (int j = 0; j < 4; j++)
                    acc[i][j] += a[i] * b[j];
        }
    }
    float bsv[4] = {0.f, 0.f, 0.f, 0.f};
    if (bias) *(float4*)bsv = *(const float4*)&bias[n0 + tx*4];
#pragma unroll
    for (int i = 0; i < 4; i++) {
        float4 r = make_float4(acc[i][0]+bsv[0], acc[i][1]+bsv[1],
                               acc[i][2]+bsv[2], acc[i][3]+bsv[3]);
        *(float4*)&C[(size_t)(m0 + (ty<<2) + i) * N + n0 + (tx<<2)] = r;
    }
}

// ---------------- LayerNorm + head transpose (+V repack) ----------------
// one warp per 64-dim row. tasks: [0,T) q-LN, [T,2T) k-LN, [2T,3T) v-copy
// task id = ((b*2048)+n)*16 + h ; T = 65536
__global__ __launch_bounds__(256) void ln_kernel(
    const float* __restrict__ lng, const float* __restrict__ lnb)
{
    const int gw   = (blockIdx.x * 256 + threadIdx.x) >> 5;
    const int lane = threadIdx.x & 31;
    const int T = BATCH * NQ * H_;  // 65536

    if (gw < 2*T) {
        const bool isq = gw < T;
        const int id = isq ? gw : gw - T;
        const int h = id & 15, n = (id >> 4) & (NQ-1), b = id >> 15;
        const float* src = isq
            ? g_rawq  + ((size_t)(b*NQ + n)) * DM + h*64
            : g_rawkv + ((size_t)(b*NC + n)) * 2 * DM + h*64;   // kv slot 0 = k
        float2 x = *(const float2*)&src[lane*2];
        float s = x.x + x.y;
#pragma unroll
        for (int o = 16; o > 0; o >>= 1) s += __shfl_xor_sync(0xffffffffu, s, o);
        const float mu = s * (1.f/64.f);
        const float dx = x.x - mu, dy = x.y - mu;
        float vv = dx*dx + dy*dy;
#pragma unroll
        for (int o = 16; o > 0; o >>= 1) vv += __shfl_xor_sync(0xffffffffu, vv, o);
        const float rstd = rsqrtf(vv * (1.f/64.f) + 1e-5f);
        float y0 = dx * rstd * lng[lane*2+0] + lnb[lane*2+0];
        float y1 = dy * rstd * lng[lane*2+1] + lnb[lane*2+1];
        if (isq) { y0 *= 8.f; y1 *= 8.f; }     // q * sqrt(head_dim)
        float* dst = (isq ? g_q : g_k) + (((size_t)(b*H_ + h))*NQ + n) * 64;
        *(float2*)&dst[lane*2] = make_float2(y0, y1);
    } else if (gw < 3*T) {
        const int id = gw - 2*T;
        const int h = id & 15, n = (id >> 4) & (NQ-1), b = id >> 15;
        const float* src = g_rawkv + (((size_t)(b*NC + n))*2 + 1) * DM + h*64;
        float* dst = g_v + (((size_t)(b*H_ + h))*NC + n) * 64;
        *(float2*)&dst[lane*2] = *(const float2*)&src[lane*2];
    }
}

// ---------------- Flash attention, fp32 SIMT ----------------
// grid: (NQ/64, B*H). block 256 (16x16), 4x4 per thread.
// smem 48KB: Qs[64][64], Kt[64(d)][64(col)] (xor-swizzled, reused as Ps), Vs[64][64]
// Kt swizzle: element (d, col) at d*64 + (((col>>2) ^ ((d>>2)&15)) << 2) + (col&3)
#define KT_IDX(d, colv) ((d)*64 + (((colv) ^ (((d)>>2) & 15)) << 2))

__global__ __launch_bounds__(256) void attn_kernel()
{
    __shared__ float sm[3 * 64 * 64];   // 48 KB
    float* Qs = sm;
    float* Kt = sm + 4096;
    float* Vs = sm + 8192;
    float* Ps = Kt;                     // reuse

    const int bh = blockIdx.y;          // b*16 + h
    const int qt = blockIdx.x;
    const size_t kvbase = (size_t)bh * NC * D_;
    const float* Qg = g_q + (size_t)bh * NQ * D_ + (size_t)qt * 64 * D_;
    const float* Kg = g_k + kvbase;
    const float* Vg = g_v + kvbase;

    const int t = threadIdx.x, tx = t & 15, ty = t >> 4;

    // load Q tile (natural layout)
#pragma unroll
    for (int i = 0; i < 4; i++) {
        int idx = t + i*256;
        int r = idx >> 4, cv = (idx & 15) << 2;
        *(float4*)&Qs[r*64 + cv] = *(const float4*)&Qg[r*64 + cv];
    }

    float m_i[4], l_i[4], oa[4][4];
#pragma unroll
    for (int i = 0; i < 4; i++) {
        m_i[i] = -1e30f; l_i[i] = 0.f;
#pragma unroll
        for (int j = 0; j < 4; j++) oa[i][j] = 0.f;
    }

    for (int kt = 0; kt < NC/64; kt++) {
        __syncthreads();   // prior P@V done -> safe to overwrite Kt/Ps, Vs
        // load K (transposed+swizzled) and V (natural)
#pragma unroll
        for (int i = 0; i < 4; i++) {
            int idx = t + i*256;
            int r = idx >> 4, cv = (idx & 15) << 2;
            const float4 kv = *(const float4*)&Kg[(size_t)kt*4096 + r*64 + cv];
            const int rv = r >> 2, rr = r & 3;
            Kt[KT_IDX(cv+0, rv) + rr] = kv.x;
            Kt[KT_IDX(cv+1, rv) + rr] = kv.y;
            Kt[KT_IDX(cv+2, rv) + rr] = kv.z;
            Kt[KT_IDX(cv+3, rv) + rr] = kv.w;
            *(float4*)&Vs[r*64 + cv] = *(const float4*)&Vg[(size_t)kt*4096 + r*64 + cv];
        }
        __syncthreads();

        // S = Q @ K^T   (4x4 per thread)
        float s[4][4] = {};
#pragma unroll
        for (int d4 = 0; d4 < 16; d4++) {
            float aq[4][4], bq[4][4];
#pragma unroll
            for (int i = 0; i < 4; i++)
                *(float4*)aq[i] = *(const float4*)&Qs[((ty<<2)+i)*64 + (d4<<2)];
#pragma unroll
            for (int dd = 0; dd < 4; dd++)
                *(float4*)bq[dd] = *(const float4*)&Kt[KT_IDX((d4<<2)+dd, tx)];
#pragma unroll
            for (int dd = 0; dd < 4; dd++)
#pragma unroll
                for (int i = 0; i < 4; i++)
#pragma unroll
                    for (int j = 0; j < 4; j++)
                        s[i][j] += aq[i][dd] * bq[dd][j];
        }

        // online softmax (row state replicated across the 16 tx lanes)
        float scale[4];
#pragma unroll
        for (int i = 0; i < 4; i++) {
            float mt = fmaxf(fmaxf(s[i][0], s[i][1]), fmaxf(s[i][2], s[i][3]));
#pragma unroll
            for (int o = 8; o > 0; o >>= 1)
                mt = fmaxf(mt, __shfl_xor_sync(0xffffffffu, mt, o, 16));
            const float mn = fmaxf(m_i[i], mt);
            float rs = 0.f;
#pragma unroll
            for (int j = 0; j < 4; j++) { s[i][j] = __expf(s[i][j] - mn); rs += s[i][j]; }
#pragma unroll
            for (int o = 8; o > 0; o >>= 1)
                rs += __shfl_xor_sync(0xffffffffu, rs, o, 16);
            scale[i] = __expf(m_i[i] - mn);
            l_i[i] = l_i[i] * scale[i] + rs;
            m_i[i] = mn;
#pragma unroll
            for (int j = 0; j < 4; j++) oa[i][j] *= scale[i];
        }

        __syncthreads();   // all S reads of Kt done -> overwrite with P
#pragma unroll
        for (int i = 0; i < 4; i++)
            *(float4*)&Ps[((ty<<2)+i)*64 + (tx<<2)] = *(float4*)s[i];
        __syncthreads();

        // O += P @ V
#pragma unroll
        for (int c4 = 0; c4 < 16; c4++) {
            float ap[4][4], bv[4][4];
#pragma unroll
            for (int i = 0; i < 4; i++)
                *(float4*)ap[i] = *(const float4*)&Ps[((ty<<2)+i)*64 + (c4<<2)];
#pragma unroll
            for (int cc = 0; cc < 4; cc++)
                *(float4*)bv[cc] = *(const float4*)&Vs[((c4<<2)+cc)*64 + (tx<<2)];
#pragma unroll
            for (int cc = 0; cc < 4; cc++)
#pragma unroll
                for (int i = 0; i < 4; i++)
#pragma unroll
                    for (int j = 0; j < 4; j++)
                        oa[i][j] += ap[i][cc] * bv[cc][j];
        }
    }

    // normalize and write O in [b, n, h*64+d] layout for the final GEMM
    const int b = bh >> 4, h = bh & 15;
#pragma unroll
    for (int i = 0; i < 4; i++) {
        const float inv = 1.f / l_i[i];
        const int qrow = qt*64 + (ty<<2) + i;
        float4 r = make_float4(oa[i][0]*inv, oa[i][1]*inv, oa[i][2]*inv, oa[i][3]*inv);
        *(float4*)&g_o[((size_t)b*NQ + qrow)*DM + h*64 + (tx<<2)] = r;
    }
}

// ---------------- launch ----------------
extern "C" void kernel_launch(void* const* d_in, const int* in_sizes, int n_in,
                              void* d_out, int out_size)
{
    const float* xq  = (const float*)d_in[0];
    const float* xc  = (const float*)d_in[1];
    const float* Wq  = (const float*)d_in[2];
    const float* Wkv = (const float*)d_in[3];
    const float* Wp  = (const float*)d_in[4];
    const float* bp  = (const float*)d_in[5];
    const float* lng = (const float*)d_in[6];
    const float* lnb = (const float*)d_in[7];
    float* out = (float*)d_out;

    float *rawq, *rawkv, *go;
    cudaGetSymbolAddress((void**)&rawq,  g_rawq);
    cudaGetSymbolAddress((void**)&rawkv, g_rawkv);
    cudaGetSymbolAddress((void**)&go,    g_o);

    // q = xq @ Wq            [4096,1024] = [4096,1024]@[1024,1024]
    gemm_kernel<<<dim3(DM/64, MQ/64), 256>>>(xq, Wq, rawq, nullptr, MQ, DM, DM);
    // kv = xc @ Wkv          [4096,2048] = [4096,1024]@[1024,2048]
    gemm_kernel<<<dim3(2*DM/64, MC/64), 256>>>(xc, Wkv, rawkv, nullptr, MC, 2*DM, DM);
    // LN(q)*8, LN(k), repack v  (3*65536 warp-tasks / 8 warps per block)
    ln_kernel<<<(3*BATCH*NQ*H_)/8, 256>>>(lng, lnb);
    // flash attention
    attn_kernel<<<dim3(NQ/64, BATCH*H_), 256>>>();
    // out = o @ Wp + bp
    gemm_kernel<<<dim3(DM/64, MQ/64), 256>>>(go, Wp, out, bp, MQ, DM, DM);
}

// round 2
// speedup vs baseline: 1.3347x; 1.3347x over previous
#include <cuda_runtime.h>
#include <math.h>

#define H_  16
#define D_  64
#define DM  1024
#define BATCH 2
#define NQ  2048
#define NC  2048
#define MQ  (BATCH*NQ)   // 4096

// ---------------- scratch ----------------
__device__ float g_rawq[MQ * DM];            // q proj out  [b*n, 1024]
__device__ float g_rawk[MQ * DM];            // k proj out  [b*n, 1024]
__device__ float g_q[BATCH*H_*NQ*D_];        // [b,h,n,d]  (LN'd, *8)
__device__ float g_k[BATCH*H_*NC*D_];        // [b,h,n,d]  (LN'd)
__device__ float g_v[BATCH*H_*NC*D_];        // [b,h,n,d]  (scatter from V proj)
__device__ float g_o[MQ * DM];               // [b,n,(h d)]

// ---------------- helpers ----------------
__device__ __forceinline__ void cvt2tf32(float x, float& hi, float& lo) {
    unsigned u;
    asm("cvt.rna.tf32.f32 %0, %1;" : "=r"(u) : "f"(x));
    hi = __uint_as_float(u);
    lo = x - hi;
}

__device__ __forceinline__ void mma_tf32(float* d, const unsigned* a, const unsigned* b) {
    asm("mma.sync.aligned.m16n8k8.row.col.f32.tf32.tf32.f32 "
        "{%0,%1,%2,%3},{%4,%5,%6,%7},{%8,%9},{%0,%1,%2,%3};"
        : "+f"(d[0]), "+f"(d[1]), "+f"(d[2]), "+f"(d[3])
        : "r"(a[0]), "r"(a[1]), "r"(a[2]), "r"(a[3]), "r"(b[0]), "r"(b[1]));
}

// ---------------- split-tf32 GEMM ----------------
// C[M,N] = A[M,K] @ B[K,N] (+bias). 256 thr, 128x128 block tile, k-chunk 32.
// 8 warps as 2(m) x 4(n); warp tile 64x32; 4x4 m16n8 mma tiles; 3xtf32.
// MODE 0: C[m*N+n] (+bias). MODE 1: scatter to g_v [b,h,n,d].
#define AS 36
#define BS 132
// smem float offsets
#define G_AH 0
#define G_AL 4608
#define G_BH 9216
#define G_BL 13440
#define G_SMEM_BYTES 70656

template<int MODE>
__global__ __launch_bounds__(256) void gemm_tf32(
    const float* __restrict__ A, const float* __restrict__ B,
    float* __restrict__ C, const float* __restrict__ bias,
    int M, int N, int K, int ldb)
{
    extern __shared__ float sm[];
    float* Ah = sm + G_AH;
    float* Al = sm + G_AL;
    float* Bh = sm + G_BH;
    float* Bl = sm + G_BL;

    const int tid  = threadIdx.x;
    const int warp = tid >> 5, lane = tid & 31;
    const int lr = lane >> 2, lc = lane & 3;
    const int wm = warp >> 2, wn = warp & 3;
    const int m0 = blockIdx.y * 128, n0 = blockIdx.x * 128;

    float acc[4][4][4];
#pragma unroll
    for (int i = 0; i < 4; i++)
#pragma unroll
        for (int j = 0; j < 4; j++)
#pragma unroll
            for (int q = 0; q < 4; q++) acc[i][j][q] = 0.f;

    for (int k0 = 0; k0 < K; k0 += 32) {
        __syncthreads();
        // load A 128x32, B 32x128, convert, store hi/lo
#pragma unroll
        for (int i = 0; i < 4; i++) {
            int lin = tid + i * 256;
            int row = lin >> 3, k4 = (lin & 7) << 2;
            float4 av = *(const float4*)&A[(size_t)(m0 + row) * K + k0 + k4];
            float4 hv, lv;
            cvt2tf32(av.x, hv.x, lv.x); cvt2tf32(av.y, hv.y, lv.y);
            cvt2tf32(av.z, hv.z, lv.z); cvt2tf32(av.w, hv.w, lv.w);
            *(float4*)&Ah[row * AS + k4] = hv;
            *(float4*)&Al[row * AS + k4] = lv;

            int kr = lin >> 5, n4 = (lin & 31) << 2;
            float4 bv = *(const float4*)&B[(size_t)(k0 + kr) * ldb + n0 + n4];
            float4 hb, lb;
            cvt2tf32(bv.x, hb.x, lb.x); cvt2tf32(bv.y, hb.y, lb.y);
            cvt2tf32(bv.z, hb.z, lb.z); cvt2tf32(bv.w, hb.w, lb.w);
            *(float4*)&Bh[kr * BS + n4] = hb;
            *(float4*)&Bl[kr * BS + n4] = lb;
        }
        __syncthreads();

#pragma unroll
        for (int kk = 0; kk < 4; kk++) {
            const int kb = kk * 8;
            unsigned ah[4][4], al[4][4];
#pragma unroll
            for (int mt = 0; mt < 4; mt++) {
                const int r0 = wm * 64 + mt * 16 + lr;
                ah[mt][0] = __float_as_uint(Ah[(r0    ) * AS + kb + lc]);
                ah[mt][1] = __float_as_uint(Ah[(r0 + 8) * AS + kb + lc]);
                ah[mt][2] = __float_as_uint(Ah[(r0    ) * AS + kb + lc + 4]);
                ah[mt][3] = __float_as_uint(Ah[(r0 + 8) * AS + kb + lc + 4]);
                al[mt][0] = __float_as_uint(Al[(r0    ) * AS + kb + lc]);
                al[mt][1] = __float_as_uint(Al[(r0 + 8) * AS + kb + lc]);
                al[mt][2] = __float_as_uint(Al[(r0    ) * AS + kb + lc + 4]);
                al[mt][3] = __float_as_uint(Al[(r0 + 8) * AS + kb + lc + 4]);
            }
#pragma unroll
            for (int nt = 0; nt < 4; nt++) {
                const int nn = wn * 32 + nt * 8 + lr;
                unsigned bh[2], bl[2];
                bh[0] = __float_as_uint(Bh[(kb + lc    ) * BS + nn]);
                bh[1] = __float_as_uint(Bh[(kb + lc + 4) * BS + nn]);
                bl[0] = __float_as_uint(Bl[(kb + lc    ) * BS + nn]);
                bl[1] = __float_as_uint(Bl[(kb + lc + 4) * BS + nn]);
#pragma unroll
                for (int mt = 0; mt < 4; mt++) {
                    mma_tf32(acc[mt][nt], ah[mt], bh);
                    mma_tf32(acc[mt][nt], ah[mt], bl);
                    mma_tf32(acc[mt][nt], al[mt], bh);
                }
            }
        }
    }

    // epilogue
#pragma unroll
    for (int mt = 0; mt < 4; mt++) {
#pragma unroll
        for (int nt = 0; nt < 4; nt++) {
            const int col = n0 + wn * 32 + nt * 8 + 2 * lc;
            float b0 = 0.f, b1 = 0.f;
            if (MODE == 0 && bias) { b0 = bias[col]; b1 = bias[col + 1]; }
#pragma unroll
            for (int half = 0; half < 2; half++) {
                const int row = m0 + wm * 64 + mt * 16 + lr + half * 8;
                float2 r = make_float2(acc[mt][nt][half * 2] + b0,
                                       acc[mt][nt][half * 2 + 1] + b1);
                if (MODE == 0) {
                    *(float2*)&C[(size_t)row * N + col] = r;
                } else {
                    const int b = row >> 11, nn2 = row & 2047;
                    const int h = col >> 6, d = col & 63;
                    *(float2*)&g_v[(((size_t)(b * H_ + h)) * NC + nn2) * 64 + d] = r;
                }
            }
        }
    }
}

// ---------------- LayerNorm + head transpose ----------------
__global__ __launch_bounds__(256) void ln_kernel(
    const float* __restrict__ lng, const float* __restrict__ lnb)
{
    const int gw   = (blockIdx.x * 256 + threadIdx.x) >> 5;
    const int lane = threadIdx.x & 31;
    const int T = BATCH * NQ * H_;  // 65536

    const bool isq = gw < T;
    const int id = isq ? gw : gw - T;
    const int h = id & 15, n = (id >> 4) & (NQ - 1), b = id >> 15;
    const float* src = (isq ? g_rawq : g_rawk) + ((size_t)(b * NQ + n)) * DM + h * 64;
    float2 x = *(const float2*)&src[lane * 2];
    float s = x.x + x.y;
#pragma unroll
    for (int o = 16; o > 0; o >>= 1) s += __shfl_xor_sync(0xffffffffu, s, o);
    const float mu = s * (1.f / 64.f);
    const float dx = x.x - mu, dy = x.y - mu;
    float vv = dx * dx + dy * dy;
#pragma unroll
    for (int o = 16; o > 0; o >>= 1) vv += __shfl_xor_sync(0xffffffffu, vv, o);
    const float rstd = rsqrtf(vv * (1.f / 64.f) + 1e-5f);
    float y0 = dx * rstd * lng[lane * 2 + 0] + lnb[lane * 2 + 0];
    float y1 = dy * rstd * lng[lane * 2 + 1] + lnb[lane * 2 + 1];
    if (isq) { y0 *= 8.f; y1 *= 8.f; }
    float* dst = (isq ? g_q : g_k) + (((size_t)(b * H_ + h)) * NQ + n) * 64;
    *(float2*)&dst[lane * 2] = make_float2(y0, y1);
}

// ---------------- Flash attention, split-tf32 mma ----------------
// grid (NQ/64, B*H). 128 threads (4 warps). Warp w owns q rows 16w..16w+15.
// 32-key blocks. smem: Qhi/lo [64][68], Khi/lo [32][68], Vhi/lo [32][68], Phi/lo [64][36]
#define QS 68
#define KS 68
#define PS 36
#define A_QH 0
#define A_QL 4352
#define A_KH 8704
#define A_KL 10880
#define A_VH 13056
#define A_VL 15232
#define A_PH 17408
#define A_PL 19712
#define A_SMEM_BYTES 88064

__global__ __launch_bounds__(128) void attn_kernel()
{
    extern __shared__ float sm[];
    float* Qh = sm + A_QH;  float* Ql = sm + A_QL;
    float* Kh = sm + A_KH;  float* Kl = sm + A_KL;
    float* Vh = sm + A_VH;  float* Vl = sm + A_VL;
    float* Ph = sm + A_PH;  float* Pl = sm + A_PL;

    const int bh = blockIdx.y, qt = blockIdx.x;
    const int tid = threadIdx.x;
    const int warp = tid >> 5, lane = tid & 31;
    const int lr = lane >> 2, lc = lane & 3;
    const int w16 = warp * 16;

    const float* Qg = g_q + ((size_t)bh * NQ + qt * 64) * 64;
    const float* Kg = g_k + (size_t)bh * NC * 64;
    const float* Vg = g_v + (size_t)bh * NC * 64;

    // load+convert Q tile (64x64)
#pragma unroll
    for (int i = 0; i < 8; i++) {
        int lin = tid + i * 128;
        int row = lin >> 4, c4 = (lin & 15) << 2;
        float4 qv = *(const float4*)&Qg[row * 64 + c4];
        float4 hv, lv;
        cvt2tf32(qv.x, hv.x, lv.x); cvt2tf32(qv.y, hv.y, lv.y);
        cvt2tf32(qv.z, hv.z, lv.z); cvt2tf32(qv.w, hv.w, lv.w);
        *(float4*)&Qh[row * QS + c4] = hv;
        *(float4*)&Ql[row * QS + c4] = lv;
    }

    float O[8][4];
#pragma unroll
    for (int i = 0; i < 8; i++)
#pragma unroll
        for (int j = 0; j < 4; j++) O[i][j] = 0.f;
    float m0 = -1e30f, m1 = -1e30f, l0 = 0.f, l1 = 0.f;

    for (int kb = 0; kb < NC / 32; kb++) {
        __syncthreads();
        // load+convert K,V block (32x64 each)
#pragma unroll
        for (int i = 0; i < 4; i++) {
            int lin = tid + i * 128;
            int row = lin >> 4, c4 = (lin & 15) << 2;
            float4 kv = *(const float4*)&Kg[(size_t)kb * 2048 + row * 64 + c4];
            float4 hv, lv;
            cvt2tf32(kv.x, hv.x, lv.x); cvt2tf32(kv.y, hv.y, lv.y);
            cvt2tf32(kv.z, hv.z, lv.z); cvt2tf32(kv.w, hv.w, lv.w);
            *(float4*)&Kh[row * KS + c4] = hv;
            *(float4*)&Kl[row * KS + c4] = lv;
            float4 vv = *(const float4*)&Vg[(size_t)kb * 2048 + row * 64 + c4];
            cvt2tf32(vv.x, hv.x, lv.x); cvt2tf32(vv.y, hv.y, lv.y);
            cvt2tf32(vv.z, hv.z, lv.z); cvt2tf32(vv.w, hv.w, lv.w);
            *(float4*)&Vh[row * KS + c4] = hv;
            *(float4*)&Vl[row * KS + c4] = lv;
        }
        __syncthreads();

        // S = Q @ K^T : warp rows 16, keys 32 -> 4 ntiles, 8 kchunks
        float S[4][4];
#pragma unroll
        for (int nt = 0; nt < 4; nt++)
#pragma unroll
            for (int j = 0; j < 4; j++) S[nt][j] = 0.f;

#pragma unroll
        for (int kc = 0; kc < 8; kc++) {
            const int kbse = kc * 8;
            unsigned ah[4], al[4];
            ah[0] = __float_as_uint(Qh[(w16 + lr    ) * QS + kbse + lc]);
            ah[1] = __float_as_uint(Qh[(w16 + lr + 8) * QS + kbse + lc]);
            ah[2] = __float_as_uint(Qh[(w16 + lr    ) * QS + kbse + lc + 4]);
            ah[3] = __float_as_uint(Qh[(w16 + lr + 8) * QS + kbse + lc + 4]);
            al[0] = __float_as_uint(Ql[(w16 + lr    ) * QS + kbse + lc]);
            al[1] = __float_as_uint(Ql[(w16 + lr + 8) * QS + kbse + lc]);
            al[2] = __float_as_uint(Ql[(w16 + lr    ) * QS + kbse + lc + 4]);
            al[3] = __float_as_uint(Ql[(w16 + lr + 8) * QS + kbse + lc + 4]);
#pragma unroll
            for (int nt = 0; nt < 4; nt++) {
                const int key = nt * 8 + lr;
                unsigned bh2[2], bl2[2];
                bh2[0] = __float_as_uint(Kh[key * KS + kbse + lc]);
                bh2[1] = __float_as_uint(Kh[key * KS + kbse + lc + 4]);
                bl2[0] = __float_as_uint(Kl[key * KS + kbse + lc]);
                bl2[1] = __float_as_uint(Kl[key * KS + kbse + lc + 4]);
                mma_tf32(S[nt], ah, bh2);
                mma_tf32(S[nt], ah, bl2);
                mma_tf32(S[nt], al, bh2);
            }
        }

        // online softmax (rows lr and lr+8; cols spread over quad lanes)
        {
            float mt0 = -1e30f, mt1 = -1e30f;
#pragma unroll
            for (int nt = 0; nt < 4; nt++) {
                mt0 = fmaxf(mt0, fmaxf(S[nt][0], S[nt][1]));
                mt1 = fmaxf(mt1, fmaxf(S[nt][2], S[nt][3]));
            }
#pragma unroll
            for (int o = 1; o <= 2; o <<= 1) {
                mt0 = fmaxf(mt0, __shfl_xor_sync(0xffffffffu, mt0, o));
                mt1 = fmaxf(mt1, __shfl_xor_sync(0xffffffffu, mt1, o));
            }
            const float mn0 = fmaxf(m0, mt0), mn1 = fmaxf(m1, mt1);
            float sum0 = 0.f, sum1 = 0.f;
#pragma unroll
            for (int nt = 0; nt < 4; nt++) {
                S[nt][0] = __expf(S[nt][0] - mn0); sum0 += S[nt][0];
                S[nt][1] = __expf(S[nt][1] - mn0); sum0 += S[nt][1];
                S[nt][2] = __expf(S[nt][2] - mn1); sum1 += S[nt][2];
                S[nt][3] = __expf(S[nt][3] - mn1); sum1 += S[nt][3];
            }
#pragma unroll
            for (int o = 1; o <= 2; o <<= 1) {
                sum0 += __shfl_xor_sync(0xffffffffu, sum0, o);
                sum1 += __shfl_xor_sync(0xffffffffu, sum1, o);
            }
            const float sc0 = __expf(m0 - mn0), sc1 = __expf(m1 - mn1);
            l0 = l0 * sc0 + sum0;  l1 = l1 * sc1 + sum1;
            m0 = mn0;  m1 = mn1;
#pragma unroll
            for (int nt = 0; nt < 8; nt++) {
                O[nt][0] *= sc0; O[nt][1] *= sc0;
                O[nt][2] *= sc1; O[nt][3] *= sc1;
            }
        }

        // write P (hi/lo) to smem; own warp rows only
#pragma unroll
        for (int nt = 0; nt < 4; nt++) {
#pragma unroll
            for (int j = 0; j < 2; j++) {
                const int col = nt * 8 + 2 * lc + j;
                float h, l;
                cvt2tf32(S[nt][j], h, l);
                Ph[(w16 + lr) * PS + col] = h;
                Pl[(w16 + lr) * PS + col] = l;
                cvt2tf32(S[nt][2 + j], h, l);
                Ph[(w16 + lr + 8) * PS + col] = h;
                Pl[(w16 + lr + 8) * PS + col] = l;
            }
        }
        __syncwarp();

        // O += P @ V : kchunks 4 (32 keys), 8 ntiles (d=64)
#pragma unroll
        for (int kc = 0; kc < 4; kc++) {
            const int kbse = kc * 8;
            unsigned ah[4], al[4];
            ah[0] = __float_as_uint(Ph[(w16 + lr    ) * PS + kbse + lc]);
            ah[1] = __float_as_uint(Ph[(w16 + lr + 8) * PS + kbse + lc]);
            ah[2] = __float_as_uint(Ph[(w16 + lr    ) * PS + kbse + lc + 4]);
            ah[3] = __float_as_uint(Ph[(w16 + lr + 8) * PS + kbse + lc + 4]);
            al[0] = __float_as_uint(Pl[(w16 + lr    ) * PS + kbse + lc]);
            al[1] = __float_as_uint(Pl[(w16 + lr + 8) * PS + kbse + lc]);
            al[2] = __float_as_uint(Pl[(w16 + lr    ) * PS + kbse + lc + 4]);
            al[3] = __float_as_uint(Pl[(w16 + lr + 8) * PS + kbse + lc + 4]);
#pragma unroll
            for (int nt = 0; nt < 8; nt++) {
                const int d = nt * 8 + lr;
                unsigned bh2[2], bl2[2];
                bh2[0] = __float_as_uint(Vh[(kbse + lc    ) * KS + d]);
                bh2[1] = __float_as_uint(Vh[(kbse + lc + 4) * KS + d]);
                bl2[0] = __float_as_uint(Vl[(kbse + lc    ) * KS + d]);
                bl2[1] = __float_as_uint(Vl[(kbse + lc + 4) * KS + d]);
                mma_tf32(O[nt], ah, bh2);
                mma_tf32(O[nt], ah, bl2);
                mma_tf32(O[nt], al, bh2);
            }
        }
        __syncwarp();
    }

    // epilogue: normalize, write [b, n, h*64+d]
    const int b = bh >> 4, h = bh & 15;
    const float inv0 = 1.f / l0, inv1 = 1.f / l1;
#pragma unroll
    for (int nt = 0; nt < 8; nt++) {
        const int d = nt * 8 + 2 * lc;
        const int r0 = qt * 64 + w16 + lr;
        *(float2*)&g_o[((size_t)b * NQ + r0) * DM + h * 64 + d] =
            make_float2(O[nt][0] * inv0, O[nt][1] * inv0);
        *(float2*)&g_o[((size_t)b * NQ + r0 + 8) * DM + h * 64 + d] =
            make_float2(O[nt][2] * inv1, O[nt][3] * inv1);
    }
}

// ---------------- launch ----------------
extern "C" void kernel_launch(void* const* d_in, const int* in_sizes, int n_in,
                              void* d_out, int out_size)
{
    const float* xq  = (const float*)d_in[0];
    const float* xc  = (const float*)d_in[1];
    const float* Wq  = (const float*)d_in[2];
    const float* Wkv = (const float*)d_in[3];
    const float* Wp  = (const float*)d_in[4];
    const float* bp  = (const float*)d_in[5];
    const float* lng = (const float*)d_in[6];
    const float* lnb = (const float*)d_in[7];
    float* out = (float*)d_out;

    float *rawq, *rawk, *go;
    cudaGetSymbolAddress((void**)&rawq, g_rawq);
    cudaGetSymbolAddress((void**)&rawk, g_rawk);
    cudaGetSymbolAddress((void**)&go,   g_o);

    cudaFuncSetAttribute((const void*)gemm_tf32<0>,
        cudaFuncAttributeMaxDynamicSharedMemorySize, G_SMEM_BYTES);
    cudaFuncSetAttribute((const void*)gemm_tf32<1>,
        cudaFuncAttributeMaxDynamicSharedMemorySize, G_SMEM_BYTES);
    cudaFuncSetAttribute((const void*)attn_kernel,
        cudaFuncAttributeMaxDynamicSharedMemorySize, A_SMEM_BYTES);

    // q = xq @ Wq
    gemm_tf32<0><<<dim3(DM/128, MQ/128), 256, G_SMEM_BYTES>>>(
        xq, Wq, rawq, nullptr, MQ, DM, DM, DM);
    // k = xc @ Wkv[:, :1024]
    gemm_tf32<0><<<dim3(DM/128, MQ/128), 256, G_SMEM_BYTES>>>(
        xc, Wkv, rawk, nullptr, MQ, DM, DM, 2*DM);
    // v = xc @ Wkv[:, 1024:]  (scattered straight into [b,h,n,d])
    gemm_tf32<1><<<dim3(DM/128, MQ/128), 256, G_SMEM_BYTES>>>(
        xc, Wkv + DM, nullptr, nullptr, MQ, DM, DM, 2*DM);
    // LN(q)*8, LN(k)
    ln_kernel<<<(2*BATCH*NQ*H_)/8, 256>>>(lng, lnb);
    // flash attention
    attn_kernel<<<dim3(NQ/64, BATCH*H_), 128, A_SMEM_BYTES>>>();
    // out = o @ Wp + bp
    gemm_tf32<0><<<dim3(DM/128, MQ/128), 256, G_SMEM_BYTES>>>(
        go, Wp, out, bp, MQ, DM, DM, DM);
}

// round 4
// speedup vs baseline: 1.8936x; 1.4188x over previous
#include <cuda_runtime.h>
#include <cstdint>
#include <math.h>

#define H_  16
#define D_  64
#define DM  1024
#define BATCH 2
#define NQ  2048
#define NC  2048
#define MQ  (BATCH*NQ)   // 4096

typedef unsigned int uint;
typedef unsigned short ushort;

// ---------------- scratch (uint4 for 16B alignment) ----------------
// activations 3-split  [m][1024] bf16 planes
__device__ uint4 g_xqh[524288], g_xqm[524288], g_xql[524288];
__device__ uint4 g_xch[524288], g_xcm[524288], g_xcl[524288];
// weights transposed [n][k] 3-split
__device__ uint4 g_wqh[131072], g_wqm[131072], g_wql[131072];
__device__ uint4 g_wkh[131072], g_wkm[131072], g_wkl[131072];
__device__ uint4 g_wvh[131072], g_wvm[131072], g_wvl[131072];
__device__ uint4 g_wph[131072], g_wpm[131072], g_wpl[131072];
// raw projections fp32
__device__ uint4 g_rawq[1048576], g_rawk[1048576];
// LN'd q,k 3-split [b,h,n,d]
__device__ uint4 g_qh[524288], g_qm[524288], g_ql[524288];
__device__ uint4 g_kh[524288], g_km[524288], g_kl[524288];
// v 2-split TRANSPOSED [b,h,d,n]
__device__ uint4 g_vh[524288], g_vm[524288];
// attention out 2-split [m][1024]
__device__ uint4 g_oh[524288], g_om[524288];

// ---------------- helpers ----------------
__device__ __forceinline__ uint smem_u32(const void* p) {
    uint a;
    asm("{ .reg .u64 t; cvta.to.shared.u64 t, %1; cvt.u32.u64 %0, t; }" : "=r"(a) : "l"(p));
    return a;
}
// pack two fp32 -> bf16x2 (e in low half = even-k element)
__device__ __forceinline__ uint pk(float e, float o) {
    uint r;
    asm("cvt.rn.bf16x2.f32 %0, %1, %2;" : "=r"(r) : "f"(o), "f"(e));
    return r;
}
__device__ __forceinline__ float lo_f(uint w) { return __uint_as_float(w << 16); }
__device__ __forceinline__ float hi_f(uint w) { return __uint_as_float(w & 0xffff0000u); }
__device__ __forceinline__ void split2(float e, float o, uint& h, uint& m) {
    h = pk(e, o);
    m = pk(e - lo_f(h), o - hi_f(h));
}
__device__ __forceinline__ void split3(float e, float o, uint& h, uint& m, uint& l) {
    h = pk(e, o);
    float re = e - lo_f(h), ro = o - hi_f(h);
    m = pk(re, ro);
    l = pk(re - lo_f(m), ro - hi_f(m));
}
__device__ __forceinline__ void mma16816(float* d, const uint* a, uint b0, uint b1) {
    asm("mma.sync.aligned.m16n8k16.row.col.f32.bf16.bf16.f32 "
        "{%0,%1,%2,%3},{%4,%5,%6,%7},{%8,%9},{%0,%1,%2,%3};"
        : "+f"(d[0]), "+f"(d[1]), "+f"(d[2]), "+f"(d[3])
        : "r"(a[0]), "r"(a[1]), "r"(a[2]), "r"(a[3]), "r"(b0), "r"(b1));
}
#define CP16(dst, src) \
    asm volatile("cp.async.ca.shared.global [%0], [%1], 16;" :: "r"(dst), "l"(src))
#define CP_COMMIT() asm volatile("cp.async.commit_group;" ::: "memory")
#define CP_WAIT1()  asm volatile("cp.async.wait_group 1;" ::: "memory")

// ---------------- prep: weight transpose + 3-split  dst[n][k] ----------------
__global__ __launch_bounds__(256) void wsplit_kernel(
    const float* __restrict__ src, int ld, ushort* H, ushort* M, ushort* L)
{
    __shared__ float t[32][33];
    const int bx = blockIdx.x * 32;   // n
    const int by = blockIdx.y * 32;   // k
    const int tid = threadIdx.x;
#pragma unroll
    for (int i = 0; i < 4; i++) {
        int idx = tid + i * 256;
        int r = idx >> 5, c = idx & 31;
        t[r][c] = src[(size_t)(by + r) * ld + bx + c];
    }
    __syncthreads();
    uint* Hw = (uint*)H; uint* Mw = (uint*)M; uint* Lw = (uint*)L;
#pragma unroll
    for (int i = 0; i < 2; i++) {
        int idx = tid + i * 256;
        int nn = idx >> 4, kw = idx & 15;
        float e = t[2 * kw][nn], o = t[2 * kw + 1][nn];
        uint h, m, l;
        split3(e, o, h, m, l);
        size_t w = (size_t)(bx + nn) * 512 + (by >> 1) + kw;
        Hw[w] = h; Mw[w] = m; Lw[w] = l;
    }
}

// ---------------- prep: activation 3-split ----------------
__global__ __launch_bounds__(256) void conv3_kernel(
    const float4* __restrict__ src, uint2* H, uint2* M, uint2* L)
{
    size_t i = (size_t)blockIdx.x * 256 + threadIdx.x;
    float4 v = src[i];
    uint h0, m0, l0, h1, m1, l1;
    split3(v.x, v.y, h0, m0, l0);
    split3(v.z, v.w, h1, m1, l1);
    H[i] = make_uint2(h0, h1);
    M[i] = make_uint2(m0, m1);
    L[i] = make_uint2(l0, l1);
}

// ---------------- GEMM: C[4096,1024] = A[4096,1024] @ BT[1024,1024]^T ----------------
// NP=6: products hh,hm,mh,hl,lh,mm (3 planes). NP=3: hh,hm,mh (2 planes).
// MODE 0: fp32 C (+bias). MODE 1: 2-split scatter into g_vh/g_vm [b,h,d,n].
// Tile 128x128, 8 warps (2m x 4n), k-chunk 32 (2 k16 slabs), 2-stage cp.async.
template<int NP, int MODE>
__global__ __launch_bounds__(256) void gemm_bf16(
    const ushort* __restrict__ Ah, const ushort* __restrict__ Am, const ushort* __restrict__ Al,
    const ushort* __restrict__ Bh, const ushort* __restrict__ Bm, const ushort* __restrict__ Bl,
    float* __restrict__ C, const float* __restrict__ bias)
{
    constexpr int APL = (NP == 6) ? 3 : 2;           // planes per operand
    constexpr int STW = 2 * APL * 2560;              // stage words
    extern __shared__ uint sw[];
    const uint smem0 = smem_u32(sw);
    const int tid = threadIdx.x, warp = tid >> 5, lane = tid & 31;
    const int lr = lane >> 2, lc = lane & 3;
    const int wm = warp >> 2, wn = warp & 3;
    const int m0 = blockIdx.y * 128, n0 = blockIdx.x * 128;

    const ushort* APl[3] = { Ah, Am, Al };
    const ushort* BPl[3] = { Bh, Bm, Bl };

    // issue cp.async for chunk ck into stage st
    auto issue = [&](int ck, int st) {
        const uint sb = smem0 + (uint)st * STW * 4;
#pragma unroll
        for (int p = 0; p < APL; p++) {
#pragma unroll
            for (int j = 0; j < 2; j++) {
                int idx = j * 256 + tid;
                int row = idx >> 2, c = idx & 3;
                const ushort* srcA = APl[p] + (size_t)(m0 + row) * 1024 + ck * 32 + c * 8;
                CP16(sb + (p * 2560 + row * 20 + c * 4) * 4, srcA);
                const ushort* srcB = BPl[p] + (size_t)(n0 + row) * 1024 + ck * 32 + c * 8;
                CP16(sb + ((APL + p) * 2560 + row * 20 + c * 4) * 4, srcB);
            }
        }
    };

    float acc[4][4][4];
#pragma unroll
    for (int i = 0; i < 4; i++)
#pragma unroll
        for (int j = 0; j < 4; j++)
#pragma unroll
            for (int q = 0; q < 4; q++) acc[i][j][q] = 0.f;

    issue(0, 0); CP_COMMIT();
    issue(1, 1); CP_COMMIT();

    for (int ck = 0; ck < 32; ck++) {
        CP_WAIT1();
        __syncthreads();
        const uint* W = sw + (ck & 1) * STW;
#pragma unroll
        for (int s = 0; s < 2; s++) {
            uint ah[4][4], am[4][4], al[4][4];
#pragma unroll
            for (int mt = 0; mt < 4; mt++) {
                const int r = wm * 64 + mt * 16 + lr;
                const int base = r * 20 + s * 8 + lc;
                ah[mt][0] = W[base];           ah[mt][1] = W[base + 160];
                ah[mt][2] = W[base + 4];       ah[mt][3] = W[base + 164];
                am[mt][0] = W[2560 + base];    am[mt][1] = W[2560 + base + 160];
                am[mt][2] = W[2560 + base + 4];am[mt][3] = W[2560 + base + 164];
                if (NP == 6) {
                    al[mt][0] = W[5120 + base];     al[mt][1] = W[5120 + base + 160];
                    al[mt][2] = W[5120 + base + 4]; al[mt][3] = W[5120 + base + 164];
                }
            }
#pragma unroll
            for (int nt = 0; nt < 4; nt++) {
                const int n = wn * 32 + nt * 8 + lr;
                const int bb = APL * 2560 + n * 20 + s * 8 + lc;
                const uint bh0 = W[bb],        bh1 = W[bb + 4];
                const uint bm0 = W[2560 + bb], bm1 = W[2560 + bb + 4];
#pragma unroll
                for (int mt = 0; mt < 4; mt++) {
                    mma16816(acc[mt][nt], ah[mt], bh0, bh1);
                    mma16816(acc[mt][nt], ah[mt], bm0, bm1);
                    mma16816(acc[mt][nt], am[mt], bh0, bh1);
                }
                if (NP == 6) {
                    const uint bl0 = W[5120 + bb], bl1 = W[5120 + bb + 4];
#pragma unroll
                    for (int mt = 0; mt < 4; mt++) {
                        mma16816(acc[mt][nt], ah[mt], bl0, bl1);
                        mma16816(acc[mt][nt], al[mt], bh0, bh1);
                        mma16816(acc[mt][nt], am[mt], bm0, bm1);
                    }
                }
            }
        }
        __syncthreads();
        if (ck + 2 < 32) issue(ck + 2, ck & 1);
        CP_COMMIT();
    }

    // epilogue
#pragma unroll
    for (int mt = 0; mt < 4; mt++) {
#pragma unroll
        for (int nt = 0; nt < 4; nt++) {
            const int col = n0 + wn * 32 + nt * 8 + 2 * lc;
            if (MODE == 0) {
                float b0 = 0.f, b1 = 0.f;
                if (bias) { b0 = bias[col]; b1 = bias[col + 1]; }
#pragma unroll
                for (int hf = 0; hf < 2; hf++) {
                    const int row = m0 + wm * 64 + mt * 16 + lr + hf * 8;
                    *(float2*)&C[(size_t)row * 1024 + col] =
                        make_float2(acc[mt][nt][hf * 2] + b0, acc[mt][nt][hf * 2 + 1] + b1);
                }
            } else {
                ushort* vh = (ushort*)g_vh;
                ushort* vm = (ushort*)g_vm;
                const int h = col >> 6, d = col & 63;
#pragma unroll
                for (int hf = 0; hf < 2; hf++) {
                    const int row = m0 + wm * 64 + mt * 16 + lr + hf * 8;
                    const int b = row >> 11, key = row & 2047;
#pragma unroll
                    for (int jj = 0; jj < 2; jj++) {
                        float v = acc[mt][nt][hf * 2 + jj];
                        uint w0, w1;
                        split2(v, 0.f, w0, w1);
                        size_t idx = ((size_t)((b * H_ + h) * 64 + d + jj)) * 2048 + key;
                        vh[idx] = (ushort)(w0 & 0xffff);
                        vm[idx] = (ushort)(w1 & 0xffff);
                    }
                }
            }
        }
    }
}

// ---------------- LayerNorm -> 3-split [b,h,n,d] ----------------
__global__ __launch_bounds__(256) void ln_kernel(
    const float* __restrict__ lng, const float* __restrict__ lnb)
{
    const int gw   = (blockIdx.x * 256 + threadIdx.x) >> 5;
    const int lane = threadIdx.x & 31;
    const int T = BATCH * NQ * H_;  // 65536

    const bool isq = gw < T;
    const int id = isq ? gw : gw - T;
    const int h = id & 15, n = (id >> 4) & (NQ - 1), b = id >> 15;
    const float* src = (isq ? (const float*)g_rawq : (const float*)g_rawk)
                     + ((size_t)(b * NQ + n)) * DM + h * 64;
    float2 x = *(const float2*)&src[lane * 2];
    float s = x.x + x.y;
#pragma unroll
    for (int o = 16; o > 0; o >>= 1) s += __shfl_xor_sync(0xffffffffu, s, o);
    const float mu = s * (1.f / 64.f);
    const float dx = x.x - mu, dy = x.y - mu;
    float vv = dx * dx + dy * dy;
#pragma unroll
    for (int o = 16; o > 0; o >>= 1) vv += __shfl_xor_sync(0xffffffffu, vv, o);
    const float rstd = rsqrtf(vv * (1.f / 64.f) + 1e-5f);
    float y0 = dx * rstd * lng[lane * 2 + 0] + lnb[lane * 2 + 0];
    float y1 = dy * rstd * lng[lane * 2 + 1] + lnb[lane * 2 + 1];
    if (isq) { y0 *= 8.f; y1 *= 8.f; }
    uint hh, mm, ll;
    split3(y0, y1, hh, mm, ll);
    const size_t w = ((size_t)((b * H_ + h) * NQ + n)) * 32 + lane;
    if (isq) {
        ((uint*)g_qh)[w] = hh; ((uint*)g_qm)[w] = mm; ((uint*)g_ql)[w] = ll;
    } else {
        ((uint*)g_kh)[w] = hh; ((uint*)g_km)[w] = mm; ((uint*)g_kl)[w] = ll;
    }
}

// ---------------- Flash attention ----------------
// grid (16, 32): q-tile 128 rows x 8 warps. 32-key blocks, 2-stage cp.async.
// smem/stage: K 3 planes [32 key][64 d] stride 36w = 3*4608B; V 2 planes [64 d][32 key] stride 20w = 2*5120B
#define AT_STAGE_B 24064
#define AT_STAGE_W 6016
#define AT_SMEM (2 * AT_STAGE_B)

__global__ __launch_bounds__(256) void attn_kernel()
{
    extern __shared__ uint sw[];
    const uint smem0 = smem_u32(sw);
    const int bh = blockIdx.y, qt = blockIdx.x;
    const int tid = threadIdx.x, warp = tid >> 5, lane = tid & 31;
    const int lr = lane >> 2, lc = lane & 3;

    // Q fragments in registers (16 rows per warp, k = d = 64 -> 4 slabs)
    uint qh[4][4], qm[4][4], ql[4][4];
    {
        const uint* Qh = (const uint*)g_qh;
        const uint* Qm = (const uint*)g_qm;
        const uint* Ql = (const uint*)g_ql;
        const size_t r0 = (size_t)bh * 2048 + qt * 128 + warp * 16 + lr;
#pragma unroll
        for (int s = 0; s < 4; s++) {
            const size_t base = r0 * 32 + 8 * s + lc;
            qh[s][0] = Qh[base];       qh[s][1] = Qh[base + 256];
            qh[s][2] = Qh[base + 4];   qh[s][3] = Qh[base + 260];
            qm[s][0] = Qm[base];       qm[s][1] = Qm[base + 256];
            qm[s][2] = Qm[base + 4];   qm[s][3] = Qm[base + 260];
            ql[s][0] = Ql[base];       ql[s][1] = Ql[base + 256];
            ql[s][2] = Ql[base + 4];   ql[s][3] = Ql[base + 260];
        }
    }

    const ushort* Kp[3] = { (const ushort*)g_kh, (const ushort*)g_km, (const ushort*)g_kl };
    const ushort* Vp[2] = { (const ushort*)g_vh, (const ushort*)g_vm };

    auto issue = [&](int kb, int st) {
        const uint sb = smem0 + (uint)st * AT_STAGE_B;
        const int n0 = kb * 32;
        {   // K: 3 planes, 32 rows x 8 chunks = 256 per plane
            const int row = tid >> 3, c = tid & 7;
#pragma unroll
            for (int p = 0; p < 3; p++) {
                const ushort* src = Kp[p] + ((size_t)bh * 2048 + n0 + row) * 64 + c * 8;
                CP16(sb + p * 4608 + row * 144 + c * 16, src);
            }
        }
        {   // V: 2 planes, 64 rows x 4 chunks
            const int row = tid >> 2, c = tid & 3;
#pragma unroll
            for (int p = 0; p < 2; p++) {
                const ushort* src = Vp[p] + ((size_t)bh * 64 + row) * 2048 + n0 + c * 8;
                CP16(sb + 13824 + p * 5120 + row * 80 + c * 16, src);
            }
        }
    };

    float O[8][4];
#pragma unroll
    for (int i = 0; i < 8; i++)
#pragma unroll
        for (int j = 0; j < 4; j++) O[i][j] = 0.f;
    float m0 = -1e30f, m1 = -1e30f, l0 = 0.f, l1 = 0.f;

    issue(0, 0); CP_COMMIT();
    issue(1, 1); CP_COMMIT();

    for (int kb = 0; kb < 64; kb++) {
        CP_WAIT1();
        __syncthreads();
        const uint* W = sw + (kb & 1) * AT_STAGE_W;

        // S = Q K^T (6-product 3-split)
        float S[4][4];
#pragma unroll
        for (int nt = 0; nt < 4; nt++)
#pragma unroll
            for (int j = 0; j < 4; j++) S[nt][j] = 0.f;
#pragma unroll
        for (int s = 0; s < 4; s++) {
#pragma unroll
            for (int nt = 0; nt < 4; nt++) {
                const uint* kbp = W + (nt * 8 + lr) * 36 + s * 8 + lc;
                const uint kh0 = kbp[0],    kh1 = kbp[4];
                const uint km0 = kbp[1152], km1 = kbp[1156];
                const uint kl0 = kbp[2304], kl1 = kbp[2308];
                mma16816(S[nt], qh[s], kh0, kh1);
                mma16816(S[nt], qh[s], km0, km1);
                mma16816(S[nt], qm[s], kh0, kh1);
                mma16816(S[nt], qh[s], kl0, kl1);
                mma16816(S[nt], ql[s], kh0, kh1);
                mma16816(S[nt], qm[s], km0, km1);
            }
        }

        // online softmax (rows lr / lr+8)
        {
            float mt0 = -1e30f, mt1 = -1e30f;
#pragma unroll
            for (int nt = 0; nt < 4; nt++) {
                mt0 = fmaxf(mt0, fmaxf(S[nt][0], S[nt][1]));
                mt1 = fmaxf(mt1, fmaxf(S[nt][2], S[nt][3]));
            }
#pragma unroll
            for (int o = 1; o <= 2; o <<= 1) {
                mt0 = fmaxf(mt0, __shfl_xor_sync(0xffffffffu, mt0, o));
                mt1 = fmaxf(mt1, __shfl_xor_sync(0xffffffffu, mt1, o));
            }
            const float mn0 = fmaxf(m0, mt0), mn1 = fmaxf(m1, mt1);
            float sum0 = 0.f, sum1 = 0.f;
#pragma unroll
            for (int nt = 0; nt < 4; nt++) {
                S[nt][0] = __expf(S[nt][0] - mn0); sum0 += S[nt][0];
                S[nt][1] = __expf(S[nt][1] - mn0); sum0 += S[nt][1];
                S[nt][2] = __expf(S[nt][2] - mn1); sum1 += S[nt][2];
                S[nt][3] = __expf(S[nt][3] - mn1); sum1 += S[nt][3];
            }
#pragma unroll
            for (int o = 1; o <= 2; o <<= 1) {
                sum0 += __shfl_xor_sync(0xffffffffu, sum0, o);
                sum1 += __shfl_xor_sync(0xffffffffu, sum1, o);
            }
            const float sc0 = __expf(m0 - mn0), sc1 = __expf(m1 - mn1);
            l0 = l0 * sc0 + sum0;  l1 = l1 * sc1 + sum1;
            m0 = mn0;  m1 = mn1;
#pragma unroll
            for (int nt = 0; nt < 8; nt++) {
                O[nt][0] *= sc0; O[nt][1] *= sc0;
                O[nt][2] *= sc1; O[nt][3] *= sc1;
            }
        }

        // P -> A-fragments directly (C-frag layout == A-frag layout)
        uint pah[2][4], pal[2][4];
#pragma unroll
        for (int ps = 0; ps < 2; ps++) {
            const int n0t = ps * 2, n1t = ps * 2 + 1;
            split2(S[n0t][0], S[n0t][1], pah[ps][0], pal[ps][0]);
            split2(S[n0t][2], S[n0t][3], pah[ps][1], pal[ps][1]);
            split2(S[n1t][0], S[n1t][1], pah[ps][2], pal[ps][2]);
            split2(S[n1t][2], S[n1t][3], pah[ps][3], pal[ps][3]);
        }

        // O += P V
        const uint* V0 = W + 3456;
#pragma unroll
        for (int ps = 0; ps < 2; ps++) {
#pragma unroll
            for (int nt = 0; nt < 8; nt++) {
                const uint* vb = V0 + (nt * 8 + lr) * 20 + ps * 8 + lc;
                const uint vh0 = vb[0],    vh1 = vb[4];
                const uint vm0 = vb[1280], vm1 = vb[1284];
                mma16816(O[nt], pah[ps], vh0, vh1);
                mma16816(O[nt], pah[ps], vm0, vm1);
                mma16816(O[nt], pal[ps], vh0, vh1);
            }
        }

        __syncthreads();
        if (kb + 2 < 64) issue(kb + 2, kb & 1);
        CP_COMMIT();
    }

    // epilogue: normalize, 2-split, write [m][1024] planes
    const int b = bh >> 4, h = bh & 15;
    const float inv0 = 1.f / l0, inv1 = 1.f / l1;
    uint* Oh = (uint*)g_oh;
    uint* Om = (uint*)g_om;
    const size_t row0 = (size_t)b * 2048 + qt * 128 + warp * 16 + lr;
#pragma unroll
    for (int nt = 0; nt < 8; nt++) {
        uint wh, wm2;
        split2(O[nt][0] * inv0, O[nt][1] * inv0, wh, wm2);
        size_t w = row0 * 512 + h * 32 + nt * 4 + lc;
        Oh[w] = wh; Om[w] = wm2;
        split2(O[nt][2] * inv1, O[nt][3] * inv1, wh, wm2);
        Oh[w + 8 * 512] = wh; Om[w + 8 * 512] = wm2;
    }
}

// ---------------- launch ----------------
extern "C" void kernel_launch(void* const* d_in, const int* in_sizes, int n_in,
                              void* d_out, int out_size)
{
    const float* xq  = (const float*)d_in[0];
    const float* xc  = (const float*)d_in[1];
    const float* Wq  = (const float*)d_in[2];
    const float* Wkv = (const float*)d_in[3];
    const float* Wp  = (const float*)d_in[4];
    const float* bp  = (const float*)d_in[5];
    const float* lng = (const float*)d_in[6];
    const float* lnb = (const float*)d_in[7];
    float* out = (float*)d_out;

    // symbol addresses
    void *xqh, *xqm, *xql, *xch, *xcm, *xcl;
    void *wqh, *wqm, *wql, *wkh, *wkm, *wkl, *wvh, *wvm, *wvl, *wph, *wpm, *wpl;
    void *rawq, *rawk, *oh, *om;
    cudaGetSymbolAddress(&xqh, g_xqh); cudaGetSymbolAddress(&xqm, g_xqm); cudaGetSymbolAddress(&xql, g_xql);
    cudaGetSymbolAddress(&xch, g_xch); cudaGetSymbolAddress(&xcm, g_xcm); cudaGetSymbolAddress(&xcl, g_xcl);
    cudaGetSymbolAddress(&wqh, g_wqh); cudaGetSymbolAddress(&wqm, g_wqm); cudaGetSymbolAddress(&wql, g_wql);
    cudaGetSymbolAddress(&wkh, g_wkh); cudaGetSymbolAddress(&wkm, g_wkm); cudaGetSymbolAddress(&wkl, g_wkl);
    cudaGetSymbolAddress(&wvh, g_wvh); cudaGetSymbolAddress(&wvm, g_wvm); cudaGetSymbolAddress(&wvl, g_wvl);
    cudaGetSymbolAddress(&wph, g_wph); cudaGetSymbolAddress(&wpm, g_wpm); cudaGetSymbolAddress(&wpl, g_wpl);
    cudaGetSymbolAddress(&rawq, g_rawq); cudaGetSymbolAddress(&rawk, g_rawk);
    cudaGetSymbolAddress(&oh, g_oh); cudaGetSymbolAddress(&om, g_om);

    const int SM6 = 2 * 6 * 2560 * 4;   // 122880
    const int SM3 = 2 * 4 * 2560 * 4;   // 81920
    cudaFuncSetAttribute((const void*)gemm_bf16<6,0>, cudaFuncAttributeMaxDynamicSharedMemorySize, SM6);
    cudaFuncSetAttribute((const void*)gemm_bf16<3,1>, cudaFuncAttributeMaxDynamicSharedMemorySize, SM3);
    cudaFuncSetAttribute((const void*)gemm_bf16<3,0>, cudaFuncAttributeMaxDynamicSharedMemorySize, SM3);
    cudaFuncSetAttribute((const void*)attn_kernel,    cudaFuncAttributeMaxDynamicSharedMemorySize, AT_SMEM);

    // prep: weights (transpose+3split), activations (3split)
    dim3 tg(32, 32);
    wsplit_kernel<<<tg, 256>>>(Wq,         1024, (ushort*)wqh, (ushort*)wqm, (ushort*)wql);
    wsplit_kernel<<<tg, 256>>>(Wkv,        2048, (ushort*)wkh, (ushort*)wkm, (ushort*)wkl);
    wsplit_kernel<<<tg, 256>>>(Wkv + 1024, 2048, (ushort*)wvh, (ushort*)wvm, (ushort*)wvl);
    wsplit_kernel<<<tg, 256>>>(Wp,         1024, (ushort*)wph, (ushort*)wpm, (ushort*)wpl);
    conv3_kernel<<<4096, 256>>>((const float4*)xq, (uint2*)xqh, (uint2*)xqm, (uint2*)xql);
    conv3_kernel<<<4096, 256>>>((const float4*)xc, (uint2*)xch, (uint2*)xcm, (uint2*)xcl);

    dim3 gg(8, 32);   // 256 CTAs
    // q/k projections: NP=6 (high precision feeds softmax)
    gemm_bf16<6,0><<<gg, 256, SM6>>>((ushort*)xqh, (ushort*)xqm, (ushort*)xql,
                                     (ushort*)wqh, (ushort*)wqm, (ushort*)wql,
                                     (float*)rawq, nullptr);
    gemm_bf16<6,0><<<gg, 256, SM6>>>((ushort*)xch, (ushort*)xcm, (ushort*)xcl,
                                     (ushort*)wkh, (ushort*)wkm, (ushort*)wkl,
                                     (float*)rawk, nullptr);
    // v projection: NP=3, scatter-transpose epilogue
    gemm_bf16<3,1><<<gg, 256, SM3>>>((ushort*)xch, (ushort*)xcm, (ushort*)xcm,
                                     (ushort*)wvh, (ushort*)wvm, (ushort*)wvm,
                                     nullptr, nullptr);
    ln_kernel<<<(2 * BATCH * NQ * H_) / 8, 256>>>(lng, lnb);
    attn_kernel<<<dim3(16, 32), 256, AT_SMEM>>>();
    // output projection: NP=3 + bias
    gemm_bf16<3,0><<<gg, 256, SM3>>>((ushort*)oh, (ushort*)om, (ushort*)om,
                                     (ushort*)wph, (ushort*)wpm, (ushort*)wpm,
                                     out, bp);
}

// round 5
// speedup vs baseline: 2.6078x; 1.3771x over previous
#include <cuda_runtime.h>
#include <cuda_fp16.h>
#include <cstdint>
#include <math.h>

#define H_  16
#define D_  64
#define DM  1024
#define BATCH 2
#define NQ  2048
#define NC  2048
#define MQ  (BATCH*NQ)   // 4096

typedef unsigned int uint;
typedef unsigned short ushort;

// ---------------- scratch (uint4 for 16B alignment) ----------------
// activations 2-split fp16 [m][1024] planes
__device__ uint4 g_xqh[524288], g_xqm[524288];
__device__ uint4 g_xch[524288], g_xcm[524288];
// weights transposed [n][k] 2-split
__device__ uint4 g_wqh[131072], g_wqm[131072];
__device__ uint4 g_wkh[131072], g_wkm[131072];
__device__ uint4 g_wvh[131072], g_wvm[131072];
__device__ uint4 g_wph[131072], g_wpm[131072];
// raw projections fp32
__device__ uint4 g_rawq[1048576], g_rawk[1048576];
// LN'd q,k 2-split [b,h,n,d]
__device__ uint4 g_qh[524288], g_qm[524288];
__device__ uint4 g_kh[524288], g_km[524288];
// v 2-split TRANSPOSED [b,h,d,n]
__device__ uint4 g_vh[524288], g_vm[524288];
// attention out 2-split [m][1024]
__device__ uint4 g_oh[524288], g_om[524288];

// ---------------- helpers ----------------
__device__ __forceinline__ uint smem_u32(const void* p) {
    uint a;
    asm("{ .reg .u64 t; cvta.to.shared.u64 t, %1; cvt.u32.u64 %0, t; }" : "=r"(a) : "l"(p));
    return a;
}
// pack two fp32 -> fp16x2 (e -> low half = even-k element)
__device__ __forceinline__ uint pkh(float e, float o) {
    uint r;
    asm("cvt.rn.f16x2.f32 %0, %1, %2;" : "=r"(r) : "f"(o), "f"(e));
    return r;
}
__device__ __forceinline__ float lo_h(uint w) {
    return __low2float(*(const __half2*)&w);
}
__device__ __forceinline__ float hi_h(uint w) {
    return __high2float(*(const __half2*)&w);
}
__device__ __forceinline__ void split2h(float e, float o, uint& h, uint& m) {
    h = pkh(e, o);
    m = pkh(e - lo_h(h), o - hi_h(h));
}
__device__ __forceinline__ void mma16816(float* d, const uint* a, uint b0, uint b1) {
    asm("mma.sync.aligned.m16n8k16.row.col.f32.f16.f16.f32 "
        "{%0,%1,%2,%3},{%4,%5,%6,%7},{%8,%9},{%0,%1,%2,%3};"
        : "+f"(d[0]), "+f"(d[1]), "+f"(d[2]), "+f"(d[3])
        : "r"(a[0]), "r"(a[1]), "r"(a[2]), "r"(a[3]), "r"(b0), "r"(b1));
}
#define CP16(dst, src) \
    asm volatile("cp.async.ca.shared.global [%0], [%1], 16;" :: "r"(dst), "l"(src))
#define CP_COMMIT() asm volatile("cp.async.commit_group;" ::: "memory")
#define CP_WAIT1()  asm volatile("cp.async.wait_group 1;" ::: "memory")

// ---------------- prep: weight transpose + 2-split  dst[n][k] ----------------
__global__ __launch_bounds__(256) void wsplit_kernel(
    const float* __restrict__ src, int ld, ushort* H, ushort* M)
{
    __shared__ float t[32][33];
    const int bx = blockIdx.x * 32;   // n
    const int by = blockIdx.y * 32;   // k
    const int tid = threadIdx.x;
#pragma unroll
    for (int i = 0; i < 4; i++) {
        int idx = tid + i * 256;
        int r = idx >> 5, c = idx & 31;
        t[r][c] = src[(size_t)(by + r) * ld + bx + c];
    }
    __syncthreads();
    uint* Hw = (uint*)H; uint* Mw = (uint*)M;
#pragma unroll
    for (int i = 0; i < 2; i++) {
        int idx = tid + i * 256;
        int nn = idx >> 4, kw = idx & 15;
        float e = t[2 * kw][nn], o = t[2 * kw + 1][nn];
        uint h, m;
        split2h(e, o, h, m);
        size_t w = (size_t)(bx + nn) * 512 + (by >> 1) + kw;
        Hw[w] = h; Mw[w] = m;
    }
}

// ---------------- prep: activation 2-split ----------------
__global__ __launch_bounds__(256) void conv2_kernel(
    const float4* __restrict__ src, uint2* H, uint2* M)
{
    size_t i = (size_t)blockIdx.x * 256 + threadIdx.x;
    float4 v = src[i];
    uint h0, m0, h1, m1;
    split2h(v.x, v.y, h0, m0);
    split2h(v.z, v.w, h1, m1);
    H[i] = make_uint2(h0, h1);
    M[i] = make_uint2(m0, m1);
}

// ---------------- GEMM: C[4096,1024] = A[4096,1024] @ BT[1024,1024]^T ----------------
// 2-split fp16, 3 products (hh, hm, mh).
// MODE 0: fp32 C (+bias). MODE 1: 2-split scatter into g_vh/g_vm [b,h,d,n].
// Tile 128x128, 8 warps (2m x 4n), k-chunk 32 (2 k16 slabs), 2-stage cp.async.
#define G_STW 10240                     // stage words: 4 planes * 2560
#define G_SMEM (2 * G_STW * 4)          // 81920 B

template<int MODE>
__global__ __launch_bounds__(256) void gemm_fp16(
    const ushort* __restrict__ Ah, const ushort* __restrict__ Am,
    const ushort* __restrict__ Bh, const ushort* __restrict__ Bm,
    float* __restrict__ C, const float* __restrict__ bias)
{
    extern __shared__ uint sw[];
    const uint smem0 = smem_u32(sw);
    const int tid = threadIdx.x, warp = tid >> 5, lane = tid & 31;
    const int lr = lane >> 2, lc = lane & 3;
    const int wm = warp >> 2, wn = warp & 3;
    const int m0 = blockIdx.y * 128, n0 = blockIdx.x * 128;

    const ushort* APl[2] = { Ah, Am };
    const ushort* BPl[2] = { Bh, Bm };

    auto issue = [&](int ck, int st) {
        const uint sb = smem0 + (uint)st * G_STW * 4;
#pragma unroll
        for (int p = 0; p < 2; p++) {
#pragma unroll
            for (int j = 0; j < 2; j++) {
                int idx = j * 256 + tid;
                int row = idx >> 2, c = idx & 3;
                const ushort* srcA = APl[p] + (size_t)(m0 + row) * 1024 + ck * 32 + c * 8;
                CP16(sb + (p * 2560 + row * 20 + c * 4) * 4, srcA);
                const ushort* srcB = BPl[p] + (size_t)(n0 + row) * 1024 + ck * 32 + c * 8;
                CP16(sb + ((2 + p) * 2560 + row * 20 + c * 4) * 4, srcB);
            }
        }
    };

    float acc[4][4][4];
#pragma unroll
    for (int i = 0; i < 4; i++)
#pragma unroll
        for (int j = 0; j < 4; j++)
#pragma unroll
            for (int q = 0; q < 4; q++) acc[i][j][q] = 0.f;

    issue(0, 0); CP_COMMIT();
    issue(1, 1); CP_COMMIT();

    for (int ck = 0; ck < 32; ck++) {
        CP_WAIT1();
        __syncthreads();
        const uint* W = sw + (ck & 1) * G_STW;
#pragma unroll
        for (int s = 0; s < 2; s++) {
            uint ah[4][4], am[4][4];
#pragma unroll
            for (int mt = 0; mt < 4; mt++) {
                const int r = wm * 64 + mt * 16 + lr;
                const int base = r * 20 + s * 8 + lc;
                ah[mt][0] = W[base];            ah[mt][1] = W[base + 160];
                ah[mt][2] = W[base + 4];        ah[mt][3] = W[base + 164];
                am[mt][0] = W[2560 + base];     am[mt][1] = W[2560 + base + 160];
                am[mt][2] = W[2560 + base + 4]; am[mt][3] = W[2560 + base + 164];
            }
#pragma unroll
            for (int nt = 0; nt < 4; nt++) {
                const int n = wn * 32 + nt * 8 + lr;
                const int bb = 2 * 2560 + n * 20 + s * 8 + lc;
                const uint bh0 = W[bb],        bh1 = W[bb + 4];
                const uint bm0 = W[2560 + bb], bm1 = W[2560 + bb + 4];
                // product-major: consecutive mma hit different accumulators
#pragma unroll
                for (int mt = 0; mt < 4; mt++) mma16816(acc[mt][nt], ah[mt], bh0, bh1);
#pragma unroll
                for (int mt = 0; mt < 4; mt++) mma16816(acc[mt][nt], ah[mt], bm0, bm1);
#pragma unroll
                for (int mt = 0; mt < 4; mt++) mma16816(acc[mt][nt], am[mt], bh0, bh1);
            }
        }
        __syncthreads();
        if (ck + 2 < 32) issue(ck + 2, ck & 1);
        CP_COMMIT();
    }

    // epilogue
#pragma unroll
    for (int mt = 0; mt < 4; mt++) {
#pragma unroll
        for (int nt = 0; nt < 4; nt++) {
            const int col = n0 + wn * 32 + nt * 8 + 2 * lc;
            if (MODE == 0) {
                float b0 = 0.f, b1 = 0.f;
                if (bias) { b0 = bias[col]; b1 = bias[col + 1]; }
#pragma unroll
                for (int hf = 0; hf < 2; hf++) {
                    const int row = m0 + wm * 64 + mt * 16 + lr + hf * 8;
                    *(float2*)&C[(size_t)row * 1024 + col] =
                        make_float2(acc[mt][nt][hf * 2] + b0, acc[mt][nt][hf * 2 + 1] + b1);
                }
            } else {
                ushort* vh = (ushort*)g_vh;
                ushort* vm = (ushort*)g_vm;
                const int h = col >> 6, d = col & 63;
#pragma unroll
                for (int hf = 0; hf < 2; hf++) {
                    const int row = m0 + wm * 64 + mt * 16 + lr + hf * 8;
                    const int b = row >> 11, key = row & 2047;
#pragma unroll
                    for (int jj = 0; jj < 2; jj++) {
                        float v = acc[mt][nt][hf * 2 + jj];
                        uint w0, w1;
                        split2h(v, 0.f, w0, w1);
                        size_t idx = ((size_t)((b * H_ + h) * 64 + d + jj)) * 2048 + key;
                        vh[idx] = (ushort)(w0 & 0xffff);
                        vm[idx] = (ushort)(w1 & 0xffff);
                    }
                }
            }
        }
    }
}

// ---------------- LayerNorm -> 2-split [b,h,n,d] ----------------
__global__ __launch_bounds__(256) void ln_kernel(
    const float* __restrict__ lng, const float* __restrict__ lnb)
{
    const int gw   = (blockIdx.x * 256 + threadIdx.x) >> 5;
    const int lane = threadIdx.x & 31;
    const int T = BATCH * NQ * H_;  // 65536

    const bool isq = gw < T;
    const int id = isq ? gw : gw - T;
    const int h = id & 15, n = (id >> 4) & (NQ - 1), b = id >> 15;
    const float* src = (isq ? (const float*)g_rawq : (const float*)g_rawk)
                     + ((size_t)(b * NQ + n)) * DM + h * 64;
    float2 x = *(const float2*)&src[lane * 2];
    float s = x.x + x.y;
#pragma unroll
    for (int o = 16; o > 0; o >>= 1) s += __shfl_xor_sync(0xffffffffu, s, o);
    const float mu = s * (1.f / 64.f);
    const float dx = x.x - mu, dy = x.y - mu;
    float vv = dx * dx + dy * dy;
#pragma unroll
    for (int o = 16; o > 0; o >>= 1) vv += __shfl_xor_sync(0xffffffffu, vv, o);
    const float rstd = rsqrtf(vv * (1.f / 64.f) + 1e-5f);
    float y0 = dx * rstd * lng[lane * 2 + 0] + lnb[lane * 2 + 0];
    float y1 = dy * rstd * lng[lane * 2 + 1] + lnb[lane * 2 + 1];
    if (isq) { y0 *= 8.f; y1 *= 8.f; }
    uint hh, mm;
    split2h(y0, y1, hh, mm);
    const size_t w = ((size_t)((b * H_ + h) * NQ + n)) * 32 + lane;
    if (isq) {
        ((uint*)g_qh)[w] = hh; ((uint*)g_qm)[w] = mm;
    } else {
        ((uint*)g_kh)[w] = hh; ((uint*)g_km)[w] = mm;
    }
}

// ---------------- Flash attention (fp16 2-split, 3 products) ----------------
// grid (16, 32): q-tile 128 rows x 8 warps. 32-key blocks, 2-stage cp.async.
// smem/stage: K 2 planes [32 key][64 d] stride 36w; V 2 planes [64 d][32 key] stride 20w
#define AT_STAGE_B 19456
#define AT_STAGE_W 4864
#define AT_SMEM (2 * AT_STAGE_B)

__global__ __launch_bounds__(256) void attn_kernel()
{
    extern __shared__ uint sw[];
    const uint smem0 = smem_u32(sw);
    const int bh = blockIdx.y, qt = blockIdx.x;
    const int tid = threadIdx.x, warp = tid >> 5, lane = tid & 31;
    const int lr = lane >> 2, lc = lane & 3;

    // Q fragments in registers (16 rows per warp, d = 64 -> 4 k16 slabs)
    uint qh[4][4], qm[4][4];
    {
        const uint* Qh = (const uint*)g_qh;
        const uint* Qm = (const uint*)g_qm;
        const size_t r0 = (size_t)bh * 2048 + qt * 128 + warp * 16 + lr;
#pragma unroll
        for (int s = 0; s < 4; s++) {
            const size_t base = r0 * 32 + 8 * s + lc;
            qh[s][0] = Qh[base];       qh[s][1] = Qh[base + 256];
            qh[s][2] = Qh[base + 4];   qh[s][3] = Qh[base + 260];
            qm[s][0] = Qm[base];       qm[s][1] = Qm[base + 256];
            qm[s][2] = Qm[base + 4];   qm[s][3] = Qm[base + 260];
        }
    }

    const ushort* Kp[2] = { (const ushort*)g_kh, (const ushort*)g_km };
    const ushort* Vp[2] = { (const ushort*)g_vh, (const ushort*)g_vm };

    auto issue = [&](int kb, int st) {
        const uint sb = smem0 + (uint)st * AT_STAGE_B;
        const int n0 = kb * 32;
        {   // K: 2 planes, 32 rows x 8 16B-chunks each
            const int row = tid >> 3, c = tid & 7;
#pragma unroll
            for (int p = 0; p < 2; p++) {
                const ushort* src = Kp[p] + ((size_t)bh * 2048 + n0 + row) * 64 + c * 8;
                CP16(sb + p * 4608 + row * 144 + c * 16, src);
            }
        }
        {   // V: 2 planes, 64 rows x 4 16B-chunks
            const int row = tid >> 2, c = tid & 3;
#pragma unroll
            for (int p = 0; p < 2; p++) {
                const ushort* src = Vp[p] + ((size_t)bh * 64 + row) * 2048 + n0 + c * 8;
                CP16(sb + 9216 + p * 5120 + row * 80 + c * 16, src);
            }
        }
    };

    float O[8][4];
#pragma unroll
    for (int i = 0; i < 8; i++)
#pragma unroll
        for (int j = 0; j < 4; j++) O[i][j] = 0.f;
    float m0 = -1e30f, m1 = -1e30f, l0 = 0.f, l1 = 0.f;

    issue(0, 0); CP_COMMIT();
    issue(1, 1); CP_COMMIT();

    for (int kb = 0; kb < 64; kb++) {
        CP_WAIT1();
        __syncthreads();
        const uint* W = sw + (kb & 1) * AT_STAGE_W;

        // S = Q K^T (3-product 2-split)
        float S[4][4];
#pragma unroll
        for (int nt = 0; nt < 4; nt++)
#pragma unroll
            for (int j = 0; j < 4; j++) S[nt][j] = 0.f;
#pragma unroll
        for (int s = 0; s < 4; s++) {
            uint kh0[4], kh1[4], km0[4], km1[4];
#pragma unroll
            for (int nt = 0; nt < 4; nt++) {
                const uint* kbp = W + (nt * 8 + lr) * 36 + s * 8 + lc;
                kh0[nt] = kbp[0];    kh1[nt] = kbp[4];
                km0[nt] = kbp[1152]; km1[nt] = kbp[1156];
            }
#pragma unroll
            for (int nt = 0; nt < 4; nt++) mma16816(S[nt], qh[s], kh0[nt], kh1[nt]);
#pragma unroll
            for (int nt = 0; nt < 4; nt++) mma16816(S[nt], qh[s], km0[nt], km1[nt]);
#pragma unroll
            for (int nt = 0; nt < 4; nt++) mma16816(S[nt], qm[s], kh0[nt], kh1[nt]);
        }

        // online softmax (rows lr / lr+8)
        {
            float mt0 = -1e30f, mt1 = -1e30f;
#pragma unroll
            for (int nt = 0; nt < 4; nt++) {
                mt0 = fmaxf(mt0, fmaxf(S[nt][0], S[nt][1]));
                mt1 = fmaxf(mt1, fmaxf(S[nt][2], S[nt][3]));
            }
#pragma unroll
            for (int o = 1; o <= 2; o <<= 1) {
                mt0 = fmaxf(mt0, __shfl_xor_sync(0xffffffffu, mt0, o));
                mt1 = fmaxf(mt1, __shfl_xor_sync(0xffffffffu, mt1, o));
            }
            const float mn0 = fmaxf(m0, mt0), mn1 = fmaxf(m1, mt1);
            float sum0 = 0.f, sum1 = 0.f;
#pragma unroll
            for (int nt = 0; nt < 4; nt++) {
                S[nt][0] = __expf(S[nt][0] - mn0); sum0 += S[nt][0];
                S[nt][1] = __expf(S[nt][1] - mn0); sum0 += S[nt][1];
                S[nt][2] = __expf(S[nt][2] - mn1); sum1 += S[nt][2];
                S[nt][3] = __expf(S[nt][3] - mn1); sum1 += S[nt][3];
            }
#pragma unroll
            for (int o = 1; o <= 2; o <<= 1) {
                sum0 += __shfl_xor_sync(0xffffffffu, sum0, o);
                sum1 += __shfl_xor_sync(0xffffffffu, sum1, o);
            }
            const float sc0 = __expf(m0 - mn0), sc1 = __expf(m1 - mn1);
            l0 = l0 * sc0 + sum0;  l1 = l1 * sc1 + sum1;
            m0 = mn0;  m1 = mn1;
#pragma unroll
            for (int nt = 0; nt < 8; nt++) {
                O[nt][0] *= sc0; O[nt][1] *= sc0;
                O[nt][2] *= sc1; O[nt][3] *= sc1;
            }
        }

        // P -> A-fragments directly (C-frag layout == A-frag layout)
        uint pah[2][4], pal[2][4];
#pragma unroll
        for (int ps = 0; ps < 2; ps++) {
            const int n0t = ps * 2, n1t = ps * 2 + 1;
            split2h(S[n0t][0], S[n0t][1], pah[ps][0], pal[ps][0]);
            split2h(S[n0t][2], S[n0t][3], pah[ps][1], pal[ps][1]);
            split2h(S[n1t][0], S[n1t][1], pah[ps][2], pal[ps][2]);
            split2h(S[n1t][2], S[n1t][3], pah[ps][3], pal[ps][3]);
        }

        // O += P V (3-product), nt processed in chunks of 4 for acc independence
        const uint* V0 = W + 2304;
#pragma unroll
        for (int ps = 0; ps < 2; ps++) {
#pragma unroll
            for (int ng = 0; ng < 2; ng++) {
                uint vh0[4], vh1[4], vm0[4], vm1[4];
#pragma unroll
                for (int q = 0; q < 4; q++) {
                    const int nt = ng * 4 + q;
                    const uint* vb = V0 + (nt * 8 + lr) * 20 + ps * 8 + lc;
                    vh0[q] = vb[0];    vh1[q] = vb[4];
                    vm0[q] = vb[1280]; vm1[q] = vb[1284];
                }
#pragma unroll
                for (int q = 0; q < 4; q++) mma16816(O[ng * 4 + q], pah[ps], vh0[q], vh1[q]);
#pragma unroll
                for (int q = 0; q < 4; q++) mma16816(O[ng * 4 + q], pah[ps], vm0[q], vm1[q]);
#pragma unroll
                for (int q = 0; q < 4; q++) mma16816(O[ng * 4 + q], pal[ps], vh0[q], vh1[q]);
            }
        }

        __syncthreads();
        if (kb + 2 < 64) issue(kb + 2, kb & 1);
        CP_COMMIT();
    }

    // epilogue: normalize, 2-split, write [m][1024] planes
    const int b = bh >> 4, h = bh & 15;
    const float inv0 = 1.f / l0, inv1 = 1.f / l1;
    uint* Oh = (uint*)g_oh;
    uint* Om = (uint*)g_om;
    const size_t row0 = (size_t)b * 2048 + qt * 128 + warp * 16 + lr;
#pragma unroll
    for (int nt = 0; nt < 8; nt++) {
        uint wh, wm2;
        split2h(O[nt][0] * inv0, O[nt][1] * inv0, wh, wm2);
        size_t w = row0 * 512 + h * 32 + nt * 4 + lc;
        Oh[w] = wh; Om[w] = wm2;
        split2h(O[nt][2] * inv1, O[nt][3] * inv1, wh, wm2);
        Oh[w + 8 * 512] = wh; Om[w + 8 * 512] = wm2;
    }
}

// ---------------- launch ----------------
extern "C" void kernel_launch(void* const* d_in, const int* in_sizes, int n_in,
                              void* d_out, int out_size)
{
    const float* xq  = (const float*)d_in[0];
    const float* xc  = (const float*)d_in[1];
    const float* Wq  = (const float*)d_in[2];
    const float* Wkv = (const float*)d_in[3];
    const float* Wp  = (const float*)d_in[4];
    const float* bp  = (const float*)d_in[5];
    const float* lng = (const float*)d_in[6];
    const float* lnb = (const float*)d_in[7];
    float* out = (float*)d_out;

    void *xqh, *xqm, *xch, *xcm;
    void *wqh, *wqm, *wkh, *wkm, *wvh, *wvm, *wph, *wpm;
    void *rawq, *rawk, *oh, *om;
    cudaGetSymbolAddress(&xqh, g_xqh); cudaGetSymbolAddress(&xqm, g_xqm);
    cudaGetSymbolAddress(&xch, g_xch); cudaGetSymbolAddress(&xcm, g_xcm);
    cudaGetSymbolAddress(&wqh, g_wqh); cudaGetSymbolAddress(&wqm, g_wqm);
    cudaGetSymbolAddress(&wkh, g_wkh); cudaGetSymbolAddress(&wkm, g_wkm);
    cudaGetSymbolAddress(&wvh, g_wvh); cudaGetSymbolAddress(&wvm, g_wvm);
    cudaGetSymbolAddress(&wph, g_wph); cudaGetSymbolAddress(&wpm, g_wpm);
    cudaGetSymbolAddress(&rawq, g_rawq); cudaGetSymbolAddress(&rawk, g_rawk);
    cudaGetSymbolAddress(&oh, g_oh); cudaGetSymbolAddress(&om, g_om);

    cudaFuncSetAttribute((const void*)gemm_fp16<0>, cudaFuncAttributeMaxDynamicSharedMemorySize, G_SMEM);
    cudaFuncSetAttribute((const void*)gemm_fp16<1>, cudaFuncAttributeMaxDynamicSharedMemorySize, G_SMEM);
    cudaFuncSetAttribute((const void*)attn_kernel,  cudaFuncAttributeMaxDynamicSharedMemorySize, AT_SMEM);

    // prep
    dim3 tg(32, 32);
    wsplit_kernel<<<tg, 256>>>(Wq,         1024, (ushort*)wqh, (ushort*)wqm);
    wsplit_kernel<<<tg, 256>>>(Wkv,        2048, (ushort*)wkh, (ushort*)wkm);
    wsplit_kernel<<<tg, 256>>>(Wkv + 1024, 2048, (ushort*)wvh, (ushort*)wvm);
    wsplit_kernel<<<tg, 256>>>(Wp,         1024, (ushort*)wph, (ushort*)wpm);
    conv2_kernel<<<4096, 256>>>((const float4*)xq, (uint2*)xqh, (uint2*)xqm);
    conv2_kernel<<<4096, 256>>>((const float4*)xc, (uint2*)xch, (uint2*)xcm);

    dim3 gg(8, 32);   // 256 CTAs
    gemm_fp16<0><<<gg, 256, G_SMEM>>>((ushort*)xqh, (ushort*)xqm,
                                      (ushort*)wqh, (ushort*)wqm, (float*)rawq, nullptr);
    gemm_fp16<0><<<gg, 256, G_SMEM>>>((ushort*)xch, (ushort*)xcm,
                                      (ushort*)wkh, (ushort*)wkm, (float*)rawk, nullptr);
    gemm_fp16<1><<<gg, 256, G_SMEM>>>((ushort*)xch, (ushort*)xcm,
                                      (ushort*)wvh, (ushort*)wvm, nullptr, nullptr);
    ln_kernel<<<(2 * BATCH * NQ * H_) / 8, 256>>>(lng, lnb);
    attn_kernel<<<dim3(16, 32), 256, AT_SMEM>>>();
    gemm_fp16<0><<<gg, 256, G_SMEM>>>((ushort*)oh, (ushort*)om,
                                      (ushort*)wph, (ushort*)wpm, out, bp);
}

// round 6
// speedup vs baseline: 3.0689x; 1.1768x over previous
#include <cuda_runtime.h>
#include <cuda_fp16.h>
#include <cstdint>
#include <math.h>

#define H_  16
#define D_  64
#define DM  1024
#define BATCH 2
#define NQ  2048
#define NC  2048
#define MQ  (BATCH*NQ)   // 4096

typedef unsigned int uint;
typedef unsigned short ushort;

// ---------------- scratch ----------------
// activations 2-split fp16 [m][1024] planes
__device__ uint4 g_xqh[524288], g_xqm[524288];
__device__ uint4 g_xch[524288], g_xcm[524288];
// weights transposed [n][k] 2-split
__device__ uint4 g_wqh[131072], g_wqm[131072];
__device__ uint4 g_wkh[131072], g_wkm[131072];
__device__ uint4 g_wvh[131072], g_wvm[131072];
__device__ uint4 g_wph[131072], g_wpm[131072];
// LN'd q,k 2-split [b,h,n,d]
__device__ uint4 g_qh[524288], g_qm[524288];
__device__ uint4 g_kh[524288], g_km[524288];
// v 2-split TRANSPOSED [b,h,d,n]
__device__ uint4 g_vh[524288], g_vm[524288];
// attention out single fp16 plane [m][1024]
__device__ uint4 g_oh[524288];

// ---------------- helpers ----------------
__device__ __forceinline__ uint smem_u32(const void* p) {
    uint a;
    asm("{ .reg .u64 t; cvta.to.shared.u64 t, %1; cvt.u32.u64 %0, t; }" : "=r"(a) : "l"(p));
    return a;
}
// pack two fp32 -> fp16x2 (e -> low half = even element)
__device__ __forceinline__ uint pkh(float e, float o) {
    uint r;
    asm("cvt.rn.f16x2.f32 %0, %1, %2;" : "=r"(r) : "f"(o), "f"(e));
    return r;
}
__device__ __forceinline__ float lo_h(uint w) { return __low2float(*(const __half2*)&w); }
__device__ __forceinline__ float hi_h(uint w) { return __high2float(*(const __half2*)&w); }
__device__ __forceinline__ void split2h(float e, float o, uint& h, uint& m) {
    h = pkh(e, o);
    m = pkh(e - lo_h(h), o - hi_h(h));
}
__device__ __forceinline__ void mma16816(float* d, const uint* a, uint b0, uint b1) {
    asm("mma.sync.aligned.m16n8k16.row.col.f32.f16.f16.f32 "
        "{%0,%1,%2,%3},{%4,%5,%6,%7},{%8,%9},{%0,%1,%2,%3};"
        : "+f"(d[0]), "+f"(d[1]), "+f"(d[2]), "+f"(d[3])
        : "r"(a[0]), "r"(a[1]), "r"(a[2]), "r"(a[3]), "r"(b0), "r"(b1));
}
#define CP16(dst, src) \
    asm volatile("cp.async.ca.shared.global [%0], [%1], 16;" :: "r"(dst), "l"(src))
#define CP_COMMIT() asm volatile("cp.async.commit_group;" ::: "memory")
#define CP_WAIT1()  asm volatile("cp.async.wait_group 1;" ::: "memory")

// ---------------- prep: all 4 weights, transpose + 2-split  dst[n][k] ----------------
__global__ __launch_bounds__(256) void wsplit_kernel(
    const float* __restrict__ Wq, const float* __restrict__ Wkv, const float* __restrict__ Wp,
    uint* qH, uint* qM, uint* kH, uint* kM, uint* vH, uint* vM, uint* pH, uint* pM)
{
    const float* src; int ld; uint *Hw, *Mw;
    switch (blockIdx.z) {
        case 0:  src = Wq;         ld = 1024; Hw = qH; Mw = qM; break;
        case 1:  src = Wkv;        ld = 2048; Hw = kH; Mw = kM; break;
        case 2:  src = Wkv + 1024; ld = 2048; Hw = vH; Mw = vM; break;
        default: src = Wp;         ld = 1024; Hw = pH; Mw = pM; break;
    }
    __shared__ float t[32][33];
    const int bx = blockIdx.x * 32;   // n
    const int by = blockIdx.y * 32;   // k
    const int tid = threadIdx.x;
#pragma unroll
    for (int i = 0; i < 4; i++) {
        int idx = tid + i * 256;
        int r = idx >> 5, c = idx & 31;
        t[r][c] = src[(size_t)(by + r) * ld + bx + c];
    }
    __syncthreads();
#pragma unroll
    for (int i = 0; i < 2; i++) {
        int idx = tid + i * 256;
        int nn = idx >> 4, kw = idx & 15;
        float e = t[2 * kw][nn], o = t[2 * kw + 1][nn];
        uint h, m;
        split2h(e, o, h, m);
        size_t w = (size_t)(bx + nn) * 512 + (by >> 1) + kw;
        Hw[w] = h; Mw[w] = m;
    }
}

// ---------------- prep: both activations 2-split ----------------
__global__ __launch_bounds__(256) void conv2_kernel(
    const float4* __restrict__ xq, const float4* __restrict__ xc,
    uint2* qH, uint2* qM, uint2* cH, uint2* cM)
{
    const bool isq = blockIdx.x < 4096;
    const size_t i = ((size_t)(isq ? blockIdx.x : blockIdx.x - 4096)) * 256 + threadIdx.x;
    float4 v = isq ? xq[i] : xc[i];
    uint h0, m0, h1, m1;
    split2h(v.x, v.y, h0, m0);
    split2h(v.z, v.w, h1, m1);
    if (isq) { qH[i] = make_uint2(h0, h1); qM[i] = make_uint2(m0, m1); }
    else     { cH[i] = make_uint2(h0, h1); cM[i] = make_uint2(m0, m1); }
}

// ---------------- GEMM: C[4096,1024] = A[4096,1024] @ BT[1024,1024]^T ----------------
// NPROD=3: A 2 planes, products hh,hm,mh. NPROD=2: A 1 plane, products hh,hm.
// MODE 0: fp32 C (+bias). MODE 1: v 2-split scatter [b,h,d,n].
// MODE 2: LayerNorm over head (64) + affine + qscale, 2-split scatter [b,h,n,d].
// Tile 128x128, 8 warps (2m x 4n), k-chunk 32, 2-stage cp.async.
template<int NPROD, int MODE>
__global__ __launch_bounds__(256) void gemm_fp16(
    const ushort* __restrict__ Ah, const ushort* __restrict__ Am,
    const ushort* __restrict__ Bh, const ushort* __restrict__ Bm,
    float* __restrict__ C, const float* __restrict__ bias,
    const float* __restrict__ lng, const float* __restrict__ lnb, float qscale,
    uint* __restrict__ dstH, uint* __restrict__ dstM)
{
    constexpr int APL = (NPROD == 3) ? 2 : 1;
    constexpr int STW = (APL + 2) * 2560;        // stage words
    extern __shared__ uint sw[];
    const uint smem0 = smem_u32(sw);
    const int tid = threadIdx.x, warp = tid >> 5, lane = tid & 31;
    const int lr = lane >> 2, lc = lane & 3;
    const int wm = warp >> 2, wn = warp & 3;
    const int m0 = blockIdx.y * 128, n0 = blockIdx.x * 128;

    auto issue = [&](int ck, int st) {
        const uint sb = smem0 + (uint)st * STW * 4;
#pragma unroll
        for (int j = 0; j < 2; j++) {
            int idx = j * 256 + tid;
            int row = idx >> 2, c = idx & 3;
            const uint off = (row * 20 + c * 4) * 4;
            CP16(sb + off, Ah + (size_t)(m0 + row) * 1024 + ck * 32 + c * 8);
            if (NPROD == 3)
                CP16(sb + 2560 * 4 + off, Am + (size_t)(m0 + row) * 1024 + ck * 32 + c * 8);
            CP16(sb + APL * 2560 * 4 + off, Bh + (size_t)(n0 + row) * 1024 + ck * 32 + c * 8);
            CP16(sb + (APL + 1) * 2560 * 4 + off, Bm + (size_t)(n0 + row) * 1024 + ck * 32 + c * 8);
        }
    };

    float acc[4][4][4];
#pragma unroll
    for (int i = 0; i < 4; i++)
#pragma unroll
        for (int j = 0; j < 4; j++)
#pragma unroll
            for (int q = 0; q < 4; q++) acc[i][j][q] = 0.f;

    issue(0, 0); CP_COMMIT();
    issue(1, 1); CP_COMMIT();

    for (int ck = 0; ck < 32; ck++) {
        CP_WAIT1();
        __syncthreads();
        const uint* W = sw + (ck & 1) * STW;
#pragma unroll
        for (int s = 0; s < 2; s++) {
            uint ah[4][4], am[4][4];
#pragma unroll
            for (int mt = 0; mt < 4; mt++) {
                const int r = wm * 64 + mt * 16 + lr;
                const int base = r * 20 + s * 8 + lc;
                ah[mt][0] = W[base];            ah[mt][1] = W[base + 160];
                ah[mt][2] = W[base + 4];        ah[mt][3] = W[base + 164];
                if (NPROD == 3) {
                    am[mt][0] = W[2560 + base];     am[mt][1] = W[2560 + base + 160];
                    am[mt][2] = W[2560 + base + 4]; am[mt][3] = W[2560 + base + 164];
                }
            }
#pragma unroll
            for (int nt = 0; nt < 4; nt++) {
                const int n = wn * 32 + nt * 8 + lr;
                const int bb = APL * 2560 + n * 20 + s * 8 + lc;
                const uint bh0 = W[bb],        bh1 = W[bb + 4];
                const uint bm0 = W[2560 + bb], bm1 = W[2560 + bb + 4];
#pragma unroll
                for (int mt = 0; mt < 4; mt++) mma16816(acc[mt][nt], ah[mt], bh0, bh1);
#pragma unroll
                for (int mt = 0; mt < 4; mt++) mma16816(acc[mt][nt], ah[mt], bm0, bm1);
                if (NPROD == 3) {
#pragma unroll
                    for (int mt = 0; mt < 4; mt++) mma16816(acc[mt][nt], am[mt], bh0, bh1);
                }
            }
        }
        __syncthreads();
        if (ck + 2 < 32) issue(ck + 2, ck & 1);
        CP_COMMIT();
    }

    if (MODE == 0) {
#pragma unroll
        for (int mt = 0; mt < 4; mt++)
#pragma unroll
            for (int nt = 0; nt < 4; nt++) {
                const int col = n0 + wn * 32 + nt * 8 + 2 * lc;
                float b0 = 0.f, b1 = 0.f;
                if (bias) { b0 = bias[col]; b1 = bias[col + 1]; }
#pragma unroll
                for (int hf = 0; hf < 2; hf++) {
                    const int row = m0 + wm * 64 + mt * 16 + lr + hf * 8;
                    *(float2*)&C[(size_t)row * 1024 + col] =
                        make_float2(acc[mt][nt][hf * 2] + b0, acc[mt][nt][hf * 2 + 1] + b1);
                }
            }
    } else if (MODE == 1) {
        ushort* vh = (ushort*)g_vh;
        ushort* vm = (ushort*)g_vm;
#pragma unroll
        for (int mt = 0; mt < 4; mt++)
#pragma unroll
            for (int nt = 0; nt < 4; nt++) {
                const int col = n0 + wn * 32 + nt * 8 + 2 * lc;
                const int h = col >> 6, d = col & 63;
#pragma unroll
                for (int hf = 0; hf < 2; hf++) {
                    const int row = m0 + wm * 64 + mt * 16 + lr + hf * 8;
                    const int b = row >> 11, key = row & 2047;
#pragma unroll
                    for (int jj = 0; jj < 2; jj++) {
                        float v = acc[mt][nt][hf * 2 + jj];
                        uint w0, w1;
                        split2h(v, 0.f, w0, w1);
                        size_t idx = ((size_t)((b * H_ + h) * 64 + d + jj)) * 2048 + key;
                        vh[idx] = (ushort)(w0 & 0xffff);
                        vm[idx] = (ushort)(w1 & 0xffff);
                    }
                }
            }
    } else {
        // MODE 2: LayerNorm epilogue. head spans warp pairs (wn0,wn1)/(wn2,wn3).
        __syncthreads();                       // all mma reads of smem done
        float2* part = (float2*)sw;            // [128 rows][4 wn]
#pragma unroll
        for (int mt = 0; mt < 4; mt++)
#pragma unroll
            for (int hf = 0; hf < 2; hf++) {
                float s1 = 0.f, s2 = 0.f;
#pragma unroll
                for (int nt = 0; nt < 4; nt++) {
                    float a = acc[mt][nt][hf * 2], b = acc[mt][nt][hf * 2 + 1];
                    s1 += a + b; s2 += a * a + b * b;
                }
#pragma unroll
                for (int o = 1; o <= 2; o <<= 1) {
                    s1 += __shfl_xor_sync(0xffffffffu, s1, o);
                    s2 += __shfl_xor_sync(0xffffffffu, s2, o);
                }
                if (lc == 0) {
                    const int r = wm * 64 + mt * 16 + lr + hf * 8;
                    part[r * 4 + wn] = make_float2(s1, s2);
                }
            }
        __syncthreads();
        // ln coefficients for this thread's 8 columns
        float gE[4], gO[4], bE[4], bO[4];
#pragma unroll
        for (int nt = 0; nt < 4; nt++) {
            const int d = ((wn & 1) * 32) + nt * 8 + 2 * lc;
            gE[nt] = lng[d]; gO[nt] = lng[d + 1];
            bE[nt] = lnb[d]; bO[nt] = lnb[d + 1];
        }
        const int wp = wn & 2;
#pragma unroll
        for (int mt = 0; mt < 4; mt++)
#pragma unroll
            for (int hf = 0; hf < 2; hf++) {
                const int r = wm * 64 + mt * 16 + lr + hf * 8;
                const float2 pa = part[r * 4 + wp], pb = part[r * 4 + wp + 1];
                const float mean = (pa.x + pb.x) * (1.f / 64.f);
                const float var  = (pa.y + pb.y) * (1.f / 64.f) - mean * mean;
                const float rstd = rsqrtf(var + 1e-5f);
                const int rowg = m0 + r;
                const int b = rowg >> 11, nn = rowg & 2047;
#pragma unroll
                for (int nt = 0; nt < 4; nt++) {
                    const int col = n0 + wn * 32 + nt * 8 + 2 * lc;
                    const int h = col >> 6, d = col & 63;
                    float y0 = ((acc[mt][nt][hf * 2]     - mean) * rstd * gE[nt] + bE[nt]) * qscale;
                    float y1 = ((acc[mt][nt][hf * 2 + 1] - mean) * rstd * gO[nt] + bO[nt]) * qscale;
                    uint wh, wm2;
                    split2h(y0, y1, wh, wm2);
                    size_t w = ((size_t)((b * H_ + h) * 2048 + nn)) * 32 + (d >> 1);
                    dstH[w] = wh; dstM[w] = wm2;
                }
            }
    }
}

// ---------------- Flash attention (S: 3-product; PV: single-P x 2-split-V) ----------------
// grid (16, 32): q-tile 128 rows x 8 warps. 32-key blocks, 2-stage cp.async.
#define AT_STAGE_B 19456
#define AT_STAGE_W 4864
#define AT_SMEM (2 * AT_STAGE_B)

__global__ __launch_bounds__(256) void attn_kernel()
{
    extern __shared__ uint sw[];
    const uint smem0 = smem_u32(sw);
    const int bh = blockIdx.y, qt = blockIdx.x;
    const int tid = threadIdx.x, warp = tid >> 5, lane = tid & 31;
    const int lr = lane >> 2, lc = lane & 3;

    // Q fragments in registers
    uint qh[4][4], qm[4][4];
    {
        const uint* Qh = (const uint*)g_qh;
        const uint* Qm = (const uint*)g_qm;
        const size_t r0 = (size_t)bh * 2048 + qt * 128 + warp * 16 + lr;
#pragma unroll
        for (int s = 0; s < 4; s++) {
            const size_t base = r0 * 32 + 8 * s + lc;
            qh[s][0] = Qh[base];       qh[s][1] = Qh[base + 256];
            qh[s][2] = Qh[base + 4];   qh[s][3] = Qh[base + 260];
            qm[s][0] = Qm[base];       qm[s][1] = Qm[base + 256];
            qm[s][2] = Qm[base + 4];   qm[s][3] = Qm[base + 260];
        }
    }

    const ushort* Kp[2] = { (const ushort*)g_kh, (const ushort*)g_km };
    const ushort* Vp[2] = { (const ushort*)g_vh, (const ushort*)g_vm };

    auto issue = [&](int kb, int st) {
        const uint sb = smem0 + (uint)st * AT_STAGE_B;
        const int n0 = kb * 32;
        {   // K: 2 planes, 32 rows x 8 16B-chunks
            const int row = tid >> 3, c = tid & 7;
#pragma unroll
            for (int p = 0; p < 2; p++) {
                const ushort* src = Kp[p] + ((size_t)bh * 2048 + n0 + row) * 64 + c * 8;
                CP16(sb + p * 4608 + row * 144 + c * 16, src);
            }
        }
        {   // V: 2 planes, 64 rows x 4 16B-chunks
            const int row = tid >> 2, c = tid & 3;
#pragma unroll
            for (int p = 0; p < 2; p++) {
                const ushort* src = Vp[p] + ((size_t)bh * 64 + row) * 2048 + n0 + c * 8;
                CP16(sb + 9216 + p * 5120 + row * 80 + c * 16, src);
            }
        }
    };

    float O[8][4];
#pragma unroll
    for (int i = 0; i < 8; i++)
#pragma unroll
        for (int j = 0; j < 4; j++) O[i][j] = 0.f;
    float m0 = -1e30f, m1 = -1e30f, l0 = 0.f, l1 = 0.f;

    issue(0, 0); CP_COMMIT();
    issue(1, 1); CP_COMMIT();

    for (int kb = 0; kb < 64; kb++) {
        CP_WAIT1();
        __syncthreads();
        const uint* W = sw + (kb & 1) * AT_STAGE_W;

        // S = Q K^T (3-product)
        float S[4][4];
#pragma unroll
        for (int nt = 0; nt < 4; nt++)
#pragma unroll
            for (int j = 0; j < 4; j++) S[nt][j] = 0.f;
#pragma unroll
        for (int s = 0; s < 4; s++) {
            uint kh0[4], kh1[4], km0[4], km1[4];
#pragma unroll
            for (int nt = 0; nt < 4; nt++) {
                const uint* kbp = W + (nt * 8 + lr) * 36 + s * 8 + lc;
                kh0[nt] = kbp[0];    kh1[nt] = kbp[4];
                km0[nt] = kbp[1152]; km1[nt] = kbp[1156];
            }
#pragma unroll
            for (int nt = 0; nt < 4; nt++) mma16816(S[nt], qh[s], kh0[nt], kh1[nt]);
#pragma unroll
            for (int nt = 0; nt < 4; nt++) mma16816(S[nt], qh[s], km0[nt], km1[nt]);
#pragma unroll
            for (int nt = 0; nt < 4; nt++) mma16816(S[nt], qm[s], kh0[nt], kh1[nt]);
        }

        // online softmax (rows lr / lr+8)
        {
            float mt0 = -1e30f, mt1 = -1e30f;
#pragma unroll
            for (int nt = 0; nt < 4; nt++) {
                mt0 = fmaxf(mt0, fmaxf(S[nt][0], S[nt][1]));
                mt1 = fmaxf(mt1, fmaxf(S[nt][2], S[nt][3]));
            }
#pragma unroll
            for (int o = 1; o <= 2; o <<= 1) {
                mt0 = fmaxf(mt0, __shfl_xor_sync(0xffffffffu, mt0, o));
                mt1 = fmaxf(mt1, __shfl_xor_sync(0xffffffffu, mt1, o));
            }
            const float mn0 = fmaxf(m0, mt0), mn1 = fmaxf(m1, mt1);
            float sum0 = 0.f, sum1 = 0.f;
#pragma unroll
            for (int nt = 0; nt < 4; nt++) {
                S[nt][0] = __expf(S[nt][0] - mn0); sum0 += S[nt][0];
                S[nt][1] = __expf(S[nt][1] - mn0); sum0 += S[nt][1];
                S[nt][2] = __expf(S[nt][2] - mn1); sum1 += S[nt][2];
                S[nt][3] = __expf(S[nt][3] - mn1); sum1 += S[nt][3];
            }
#pragma unroll
            for (int o = 1; o <= 2; o <<= 1) {
                sum0 += __shfl_xor_sync(0xffffffffu, sum0, o);
                sum1 += __shfl_xor_sync(0xffffffffu, sum1, o);
            }
            const float sc0 = __expf(m0 - mn0), sc1 = __expf(m1 - mn1);
            l0 = l0 * sc0 + sum0;  l1 = l1 * sc1 + sum1;
            m0 = mn0;  m1 = mn1;
#pragma unroll
            for (int nt = 0; nt < 8; nt++) {
                O[nt][0] *= sc0; O[nt][1] *= sc0;
                O[nt][2] *= sc1; O[nt][3] *= sc1;
            }
        }

        // P -> single-plane A-fragments (C-frag layout == A-frag layout)
        uint pah[2][4];
#pragma unroll
        for (int ps = 0; ps < 2; ps++) {
            const int n0t = ps * 2, n1t = ps * 2 + 1;
            pah[ps][0] = pkh(S[n0t][0], S[n0t][1]);
            pah[ps][1] = pkh(S[n0t][2], S[n0t][3]);
            pah[ps][2] = pkh(S[n1t][0], S[n1t][1]);
            pah[ps][3] = pkh(S[n1t][2], S[n1t][3]);
        }

        // O += P V (2-product: P x Vhi, P x Vmid)
        const uint* V0 = W + 2304;
#pragma unroll
        for (int ps = 0; ps < 2; ps++) {
#pragma unroll
            for (int ng = 0; ng < 2; ng++) {
                uint vh0[4], vh1[4], vm0[4], vm1[4];
#pragma unroll
                for (int q = 0; q < 4; q++) {
                    const int nt = ng * 4 + q;
                    const uint* vb = V0 + (nt * 8 + lr) * 20 + ps * 8 + lc;
                    vh0[q] = vb[0];    vh1[q] = vb[4];
                    vm0[q] = vb[1280]; vm1[q] = vb[1284];
                }
#pragma unroll
                for (int q = 0; q < 4; q++) mma16816(O[ng * 4 + q], pah[ps], vh0[q], vh1[q]);
#pragma unroll
                for (int q = 0; q < 4; q++) mma16816(O[ng * 4 + q], pah[ps], vm0[q], vm1[q]);
            }
        }

        __syncthreads();
        if (kb + 2 < 64) issue(kb + 2, kb & 1);
        CP_COMMIT();
    }

    // epilogue: normalize, single fp16 plane, [m][1024]
    const int b = bh >> 4, h = bh & 15;
    const float inv0 = 1.f / l0, inv1 = 1.f / l1;
    uint* Oh = (uint*)g_oh;
    const size_t row0 = (size_t)b * 2048 + qt * 128 + warp * 16 + lr;
#pragma unroll
    for (int nt = 0; nt < 8; nt++) {
        size_t w = row0 * 512 + h * 32 + nt * 4 + lc;
        Oh[w] = pkh(O[nt][0] * inv0, O[nt][1] * inv0);
        Oh[w + 8 * 512] = pkh(O[nt][2] * inv1, O[nt][3] * inv1);
    }
}

// ---------------- launch ----------------
extern "C" void kernel_launch(void* const* d_in, const int* in_sizes, int n_in,
                              void* d_out, int out_size)
{
    const float* xq  = (const float*)d_in[0];
    const float* xc  = (const float*)d_in[1];
    const float* Wq  = (const float*)d_in[2];
    const float* Wkv = (const float*)d_in[3];
    const float* Wp  = (const float*)d_in[4];
    const float* bp  = (const float*)d_in[5];
    const float* lng = (const float*)d_in[6];
    const float* lnb = (const float*)d_in[7];
    float* out = (float*)d_out;

    void *xqh, *xqm, *xch, *xcm;
    void *wqh, *wqm, *wkh, *wkm, *wvh, *wvm, *wph, *wpm;
    void *qh, *qm, *kh, *km, *oh;
    cudaGetSymbolAddress(&xqh, g_xqh); cudaGetSymbolAddress(&xqm, g_xqm);
    cudaGetSymbolAddress(&xch, g_xch); cudaGetSymbolAddress(&xcm, g_xcm);
    cudaGetSymbolAddress(&wqh, g_wqh); cudaGetSymbolAddress(&wqm, g_wqm);
    cudaGetSymbolAddress(&wkh, g_wkh); cudaGetSymbolAddress(&wkm, g_wkm);
    cudaGetSymbolAddress(&wvh, g_wvh); cudaGetSymbolAddress(&wvm, g_wvm);
    cudaGetSymbolAddress(&wph, g_wph); cudaGetSymbolAddress(&wpm, g_wpm);
    cudaGetSymbolAddress(&qh, g_qh);   cudaGetSymbolAddress(&qm, g_qm);
    cudaGetSymbolAddress(&kh, g_kh);   cudaGetSymbolAddress(&km, g_km);
    cudaGetSymbolAddress(&oh, g_oh);

    const int SM3 = 2 * 4 * 2560 * 4;   // 81920
    const int SM2 = 2 * 3 * 2560 * 4;   // 61440
    cudaFuncSetAttribute((const void*)gemm_fp16<3,2>, cudaFuncAttributeMaxDynamicSharedMemorySize, SM3);
    cudaFuncSetAttribute((const void*)gemm_fp16<2,1>, cudaFuncAttributeMaxDynamicSharedMemorySize, SM2);
    cudaFuncSetAttribute((const void*)gemm_fp16<2,0>, cudaFuncAttributeMaxDynamicSharedMemorySize, SM2);
    cudaFuncSetAttribute((const void*)attn_kernel,    cudaFuncAttributeMaxDynamicSharedMemorySize, AT_SMEM);

    // prep (2 launches)
    wsplit_kernel<<<dim3(32, 32, 4), 256>>>(Wq, Wkv, Wp,
        (uint*)wqh, (uint*)wqm, (uint*)wkh, (uint*)wkm,
        (uint*)wvh, (uint*)wvm, (uint*)wph, (uint*)wpm);
    conv2_kernel<<<8192, 256>>>((const float4*)xq, (const float4*)xc,
        (uint2*)xqh, (uint2*)xqm, (uint2*)xch, (uint2*)xcm);

    dim3 gg(8, 32);   // 256 CTAs
    // q-proj + LN + *8  (3-product)
    gemm_fp16<3,2><<<gg, 256, SM3>>>((ushort*)xqh, (ushort*)xqm,
        (ushort*)wqh, (ushort*)wqm, nullptr, nullptr, lng, lnb, 8.f,
        (uint*)qh, (uint*)qm);
    // k-proj + LN  (3-product)
    gemm_fp16<3,2><<<gg, 256, SM3>>>((ushort*)xch, (ushort*)xcm,
        (ushort*)wkh, (ushort*)wkm, nullptr, nullptr, lng, lnb, 1.f,
        (uint*)kh, (uint*)km);
    // v-proj (2-product, A hi-plane only), scatter-transpose
    gemm_fp16<2,1><<<gg, 256, SM2>>>((ushort*)xch, nullptr,
        (ushort*)wvh, (ushort*)wvm, nullptr, nullptr, nullptr, nullptr, 0.f,
        nullptr, nullptr);
    // flash attention (launch #5 -> ncu capture slot)
    attn_kernel<<<dim3(16, 32), 256, AT_SMEM>>>();
    // o-proj (2-product, A = single-plane attention output) + bias
    gemm_fp16<2,0><<<gg, 256, SM2>>>((ushort*)oh, nullptr,
        (ushort*)wph, (ushort*)wpm, out, bp, nullptr, nullptr, 0.f,
        nullptr, nullptr);
}